// round 6
// baseline (speedup 1.0000x reference)
#include <cuda_runtime.h>
#include <math.h>
#include <float.h>
#include <stdint.h>

#define N_NODES 16384
#define D 128
#define BATCH 4
#define WPRIME (0.05f/1.05f)

#define KS 64                    // split-K factor
#define CHUNK (N_NODES / KS)     // 256 nodes per block
#define STAGES 4
#define SROW 136                 // smem row stride (floats), conflict-free fragments

// ---------------- device scratch (no allocations allowed) ----------------
__device__ float g_Rm[BATCH * D * D];
__device__ float g_Rp[(size_t)BATCH * KS * D * D];
__device__ int   g_rowptr[N_NODES + 1];
__device__ float g_partial[BATCH];
// per node 8 rows x 128: [Z0,Z1,Z2,y, LJ0,LJ1,LJ2, gy]
__device__ float g_pan[(size_t)BATCH * N_NODES * 1024];

// ---------------- K1: CSR row pointers (e0 sorted ascending) ----------------
__global__ void rowptr_kernel(const int* __restrict__ e0, int E) {
    int n = blockIdx.x * blockDim.x + threadIdx.x;
    if (n > N_NODES) return;
    int lo = 0, hi = E;
    while (lo < hi) {
        int mid = (lo + hi) >> 1;
        if (e0[mid] < n) lo = mid + 1; else hi = mid;
    }
    g_rowptr[n] = lo;
}

// ---------------- K2a: build per-node panels ----------------
__global__ void __launch_bounds__(256)
build_kernel(const float* __restrict__ x, const float* __restrict__ J,
             const int* __restrict__ e1arr) {
    const int b = blockIdx.y;
    const int n = blockIdx.x * 2 + (threadIdx.x >> 7);
    const int c = threadIdx.x & 127;

    const float* xb = x + (size_t)b * N_NODES * 3;
    const float* Jb = J + (size_t)b * N_NODES * 3 * D;

    const float* Jn = Jb + (size_t)(3 * n) * D + c;
    const float Jn0 = Jn[0], Jn1 = Jn[D], Jn2 = Jn[2 * D];
    const float xn0 = xb[3 * n], xn1 = xb[3 * n + 1], xn2 = xb[3 * n + 2];

    float nb0 = 0.f, nb1 = 0.f, nb2 = 0.f;
    float T0 = 0.f, T1 = 0.f, T2 = 0.f, u = 0.f;
    float deg = 0.f, s0 = 0.f, s1 = 0.f, s2 = 0.f, G = 0.f;
    float c00 = 0.f, c01 = 0.f, c02 = 0.f, c11 = 0.f, c12 = 0.f, c22 = 0.f;

    const int eBeg = g_rowptr[n], eEnd = g_rowptr[n + 1];
#pragma unroll 2
    for (int e = eBeg; e < eEnd; ++e) {
        const int m = e1arr[e];
        const float v0 = xn0 - xb[3 * m];
        const float v1 = xn1 - xb[3 * m + 1];
        const float v2 = xn2 - xb[3 * m + 2];
        const float* Jm = Jb + (size_t)(3 * m) * D + c;
        const float Jm0 = Jm[0], Jm1 = Jm[D], Jm2 = Jm[2 * D];
        nb0 += Jm0; nb1 += Jm1; nb2 += Jm2;
        T0 += v1 * Jm2 - v2 * Jm1;
        T1 += v2 * Jm0 - v0 * Jm2;
        T2 += v0 * Jm1 - v1 * Jm0;
        u  += v0 * Jm0 + v1 * Jm1 + v2 * Jm2;
        deg += 1.0f; s0 += v0; s1 += v1; s2 += v2;
        const float vv = v0 * v0 + v1 * v1 + v2 * v2;
        G += vv;
        c00 += vv - v0 * v0; c01 -= v0 * v1; c02 -= v0 * v2;
        c11 += vv - v1 * v1; c12 -= v1 * v2; c22 += vv - v2 * v2;
    }

    const float LJ0 = 2.0f * (deg * Jn0 - nb0);
    const float LJ1 = 2.0f * (deg * Jn1 - nb1);
    const float LJ2 = 2.0f * (deg * Jn2 - nb2);
    const float B0 = T0 + s2 * Jn1 - s1 * Jn2;
    const float B1 = T1 - s2 * Jn0 + s0 * Jn2;
    const float B2 = T2 + s1 * Jn0 - s0 * Jn1;
    const float y = u - (s0 * Jn0 + s1 * Jn1 + s2 * Jn2);
    // Cholesky C = L L^T, Z = L^{-1} BTJ
    const float l00 = sqrtf(c00);
    const float il00 = 1.0f / l00;
    const float l10 = c01 * il00, l20 = c02 * il00;
    const float l11 = sqrtf(c11 - l10 * l10);
    const float il11 = 1.0f / l11;
    const float l21 = (c12 - l20 * l10) * il11;
    const float l22 = sqrtf(c22 - l20 * l20 - l21 * l21);
    const float il22 = 1.0f / l22;
    const float Z0 = B0 * il00;
    const float Z1 = (B1 - l10 * Z0) * il11;
    const float Z2 = (B2 - l20 * Z0 - l21 * Z1) * il22;
    const float Ginv = (G < 1e-6f) ? 0.0f : 1.0f / G;

    float* P = g_pan + ((size_t)b * N_NODES + n) * 1024 + c;
    P[0*128] = Z0;   P[1*128] = Z1;   P[2*128] = Z2;   P[3*128] = y;
    P[4*128] = LJ0;  P[5*128] = LJ1;  P[6*128] = LJ2;
    P[7*128] = -(WPRIME * Ginv) * y;
}

// ---------------- K2b: TF32 tensor-core split-K GEMM (slim panels) ----------------
// smem rows/node: 0:J0 1:J1 2:J2 3:Z0 4:Z1 5:Z2 6:y 7:ZERO 8:LJ0 9:LJ1 10:LJ2 11:gy
// A k-row r -> smem row r.  B k-row r -> {8,9,10, 3-,4-,5-, 11, 7} (- = sign flip)
__device__ __forceinline__ void cp_async16(void* dst_smem, const void* src) {
    uint32_t d = (uint32_t)__cvta_generic_to_shared(dst_smem);
    asm volatile("cp.async.cg.shared.global [%0], [%1], 16;" :: "r"(d), "l"(src));
}
__device__ __forceinline__ void cp_commit() { asm volatile("cp.async.commit_group;"); }
template<int NN> __device__ __forceinline__ void cp_wait() {
    asm volatile("cp.async.wait_group %0;" :: "n"(NN));
}
__device__ __forceinline__ uint32_t tf32c(float f) {
    uint32_t u; asm("cvt.rna.tf32.f32 %0, %1;" : "=r"(u) : "f"(f)); return u;
}
__device__ __forceinline__ void mma_tf32(float* d, uint32_t a0, uint32_t a1,
                                         uint32_t a2, uint32_t a3,
                                         uint32_t b0, uint32_t b1) {
    asm volatile(
        "mma.sync.aligned.m16n8k8.row.col.f32.tf32.tf32.f32 "
        "{%0,%1,%2,%3}, {%4,%5,%6,%7}, {%8,%9}, {%0,%1,%2,%3};"
        : "+f"(d[0]), "+f"(d[1]), "+f"(d[2]), "+f"(d[3])
        : "r"(a0), "r"(a1), "r"(a2), "r"(a3), "r"(b0), "r"(b1));
}

__global__ void __launch_bounds__(256, 2)
gemm_kernel(const float* __restrict__ J) {
    __shared__ __align__(16) float sm[STAGES][12][SROW];

    const int b = blockIdx.y, ks = blockIdx.x;
    const int t = threadIdx.x;
    const int wid = t >> 5, lane = t & 31;
    const int wm = (wid >> 2) * 64;
    const int wn = (wid & 3) * 32;
    const int r0 = lane >> 2, kc = lane & 3;

    const int nodeBase = ks * CHUNK;
    const float* Jb = J + (size_t)b * N_NODES * 3 * D;
    const float* Pb = g_pan + ((size_t)b * N_NODES + nodeBase) * 1024;

    // zero row 7 of each stage (the k-padding row); never written again
    for (int idx = t; idx < STAGES * SROW; idx += 256)
        sm[idx / SROW][7][idx % SROW] = 0.0f;

    // per-lane B-fragment row LUT + sign (loop-invariant)
    const int   brow0 = (kc < 3) ? 8 + kc : 3;
    const float bsgn0 = (kc < 3) ? 1.0f : -1.0f;
    const int   brow1 = (kc < 2) ? 4 + kc : ((kc == 2) ? 11 : 7);
    const float bsgn1 = (kc < 2) ? -1.0f : 1.0f;

    float acc[4][4][4];
#pragma unroll
    for (int i = 0; i < 4; i++)
#pragma unroll
        for (int j = 0; j < 4; j++)
#pragma unroll
            for (int r = 0; r < 4; r++) acc[i][j][r] = 0.0f;

    auto issue = [&](int it) {
        const int stg = it & (STAGES - 1);
        const float* psrc = Pb + (size_t)it * 1024;
        {   // panel: 256 x 16B -> smem rows 3..6, 8..11
            const int prow = t >> 5;
            const int srow = (prow < 4) ? 3 + prow : 4 + prow;
            cp_async16(&sm[stg][srow][(t & 31) * 4], psrc + t * 4);
        }
        if (t < 96) {   // J: 96 x 16B -> smem rows 0..2
            const float* jsrc = Jb + (size_t)(3 * (nodeBase + it)) * D;
            cp_async16(&sm[stg][t >> 5][(t & 31) * 4], jsrc + t * 4);
        }
    };

    for (int s = 0; s < STAGES - 1; s++) { issue(s); cp_commit(); }

    for (int it = 0; it < CHUNK; ++it) {
        const int stg = it & (STAGES - 1);
        if (it + STAGES - 1 < CHUNK) issue(it + STAGES - 1);
        cp_commit();
        cp_wait<STAGES - 1>();
        __syncthreads();

        const float* S = &sm[stg][0][0];

        uint32_t bb[4][2];
#pragma unroll
        for (int nt = 0; nt < 4; nt++) {
            const int n = wn + nt * 8 + r0;
            bb[nt][0] = tf32c(bsgn0 * S[brow0 * SROW + n]);
            bb[nt][1] = tf32c(bsgn1 * S[brow1 * SROW + n]);
        }
#pragma unroll
        for (int mt = 0; mt < 4; mt++) {
            const int m = wm + mt * 16 + r0;
            const uint32_t a0 = tf32c(S[kc * SROW + m]);
            const uint32_t a1 = tf32c(S[kc * SROW + m + 8]);
            const uint32_t a2 = tf32c(S[(kc + 4) * SROW + m]);
            const uint32_t a3 = tf32c(S[(kc + 4) * SROW + m + 8]);
#pragma unroll
            for (int nt = 0; nt < 4; nt++)
                mma_tf32(acc[mt][nt], a0, a1, a2, a3, bb[nt][0], bb[nt][1]);
        }
        __syncthreads();
    }

    float* out = g_Rp + (((size_t)b * KS + ks) << 14);
#pragma unroll
    for (int mt = 0; mt < 4; mt++) {
        const int m = wm + mt * 16 + r0;
#pragma unroll
        for (int nt = 0; nt < 4; nt++) {
            const int n = wn + nt * 8 + 2 * kc;
            *(float2*)&out[m * 128 + n]       = make_float2(acc[mt][nt][0], acc[mt][nt][1]);
            *(float2*)&out[(m + 8) * 128 + n] = make_float2(acc[mt][nt][2], acc[mt][nt][3]);
        }
    }
}

// ---------------- K2c: reduce split-K partials ----------------
__global__ void reduce_kernel() {
    const int idx = blockIdx.x * 256 + threadIdx.x;
    const int b = idx >> 14;
    const float* p = g_Rp + (((size_t)b * KS) << 14) + (idx & 16383);
    float s = 0.0f;
#pragma unroll 8
    for (int k = 0; k < KS; k++) s += p[(size_t)k << 14];
    g_Rm[idx] = s;
}

// ---------------- 256-thread block reductions ----------------
__device__ __forceinline__ float brs256(float v, float* red) {
#pragma unroll
    for (int off = 16; off > 0; off >>= 1) v += __shfl_down_sync(0xffffffffu, v, off);
    if ((threadIdx.x & 31) == 0) red[threadIdx.x >> 5] = v;
    __syncthreads();
    if (threadIdx.x == 0) {
        float s = 0.f;
#pragma unroll
        for (int i = 0; i < 8; i++) s += red[i];
        red[0] = s;
    }
    __syncthreads();
    const float r = red[0];
    __syncthreads();
    return r;
}
__device__ __forceinline__ float brmin256(float v, float* red) {
#pragma unroll
    for (int off = 16; off > 0; off >>= 1) v = fminf(v, __shfl_down_sync(0xffffffffu, v, off));
    if ((threadIdx.x & 31) == 0) red[threadIdx.x >> 5] = v;
    __syncthreads();
    if (threadIdx.x == 0) {
        float s = red[0];
#pragma unroll
        for (int i = 1; i < 8; i++) s = fminf(s, red[i]);
        red[0] = s;
    }
    __syncthreads();
    const float r = red[0];
    __syncthreads();
    return r;
}
__device__ __forceinline__ float brmax256(float v, float* red) {
#pragma unroll
    for (int off = 16; off > 0; off >>= 1) v = fmaxf(v, __shfl_down_sync(0xffffffffu, v, off));
    if ((threadIdx.x & 31) == 0) red[threadIdx.x >> 5] = v;
    __syncthreads();
    if (threadIdx.x == 0) {
        float s = red[0];
#pragma unroll
        for (int i = 1; i < 8; i++) s = fmaxf(s, red[i]);
        red[0] = s;
    }
    __syncthreads();
    const float r = red[0];
    __syncthreads();
    return r;
}

// ---------------- K3: Householder + Sturm, 256 threads (2 per row) ----------------
#define ASTR 132
#define SMEM_EIG ((128 * ASTR + 4 * 128 + 256 + 32) * 4)

__global__ void eigen_kernel() {
    extern __shared__ float smE[];
    float* A   = smE;                  // 128 x ASTR
    float* uu  = A + 128 * ASTR;       // 128
    float* qq  = uu + 128;             // 128
    float* dd  = qq + 128;             // 128
    float* ee  = dd + 128;             // 128
    float* pp  = ee + 128;             // 256 partial dots
    float* red = pp + 256;             // 32

    const int b = blockIdx.x;
    const int t = threadIdx.x;
    const int r = t & 127;
    const int h = t >> 7;              // half selector
    const float* R = g_Rm + (size_t)b * D * D;

    // load + symmetrize (each thread covers 64 rows, column r)
    for (int i = h; i < 128; i += 2)
        A[i * ASTR + r] = 0.5f * (R[i * 128 + r] + R[r * 128 + i]);
    __syncthreads();

    for (int k = 0; k < 126; k++) {
        const float xi = (h == 0 && r > k) ? A[r * ASTR + k] : 0.0f;
        const float sig = brs256(xi * xi, red);
        const float x0 = A[(k + 1) * ASTR + k];
        const float nrm = sqrtf(sig);
        const float alpha = (x0 >= 0.0f) ? -nrm : nrm;
        const float H = sig - alpha * x0;
        if (t == 0) ee[k + 1] = alpha;
        if (h == 0) uu[r] = (r > k) ? (xi - ((r == k + 1) ? alpha : 0.0f)) : 0.0f;
        __syncthreads();
        if (H > 1e-32f) {
            const float invH = 1.0f / H;
            const int j0 = (k + 1) & ~3;
            const int js = (j0 > h * 64) ? j0 : h * 64;
            const int mlen = ((h * 64 + 64) - js) >> 2;    // <=0 -> skip
            float p_part = 0.0f;
            if (r > k && mlen > 0) {
                const float4* Ar4 = (const float4*)(A + r * ASTR + js);
                const float4* U4  = (const float4*)(uu + js);
                float pa0 = 0.f, pa1 = 0.f, pa2 = 0.f, pa3 = 0.f;
#pragma unroll 4
                for (int q = 0; q < mlen; q++) {
                    const float4 a = Ar4[q], u4 = U4[q];
                    if ((q & 3) == 0) pa0 += a.x * u4.x + a.y * u4.y + a.z * u4.z + a.w * u4.w;
                    else if ((q & 3) == 1) pa1 += a.x * u4.x + a.y * u4.y + a.z * u4.z + a.w * u4.w;
                    else if ((q & 3) == 2) pa2 += a.x * u4.x + a.y * u4.y + a.z * u4.z + a.w * u4.w;
                    else pa3 += a.x * u4.x + a.y * u4.y + a.z * u4.z + a.w * u4.w;
                }
                p_part = (pa0 + pa1) + (pa2 + pa3);
            }
            pp[t] = p_part;
            const float ur = uu[r];
            const float Ksum = brs256(ur * p_part * invH, red);   // K = sum_r u_r p_r / H
            const float Kc = Ksum * 0.5f * invH;
            if (h == 0) qq[r] = (pp[r] + pp[r + 128]) * invH - Kc * ur;
            __syncthreads();
            if (r > k && mlen > 0) {
                float4* Ar4 = (float4*)(A + r * ASTR + js);
                const float4* U4 = (const float4*)(uu + js);
                const float4* Q4 = (const float4*)(qq + js);
                const float uif = ur, qif = qq[r];
#pragma unroll 4
                for (int q = 0; q < mlen; q++) {
                    float4 a = Ar4[q];
                    const float4 u4 = U4[q], q4 = Q4[q];
                    a.x -= uif * q4.x + qif * u4.x;
                    a.y -= uif * q4.y + qif * u4.y;
                    a.z -= uif * q4.z + qif * u4.z;
                    a.w -= uif * q4.w + qif * u4.w;
                    Ar4[q] = a;
                }
            }
        }
        __syncthreads();
    }

    if (h == 0) {
        dd[r] = A[r * ASTR + r];
        if (r == 0) ee[0] = 0.0f;
        if (r == 127) ee[127] = A[127 * ASTR + 126];
    }
    __syncthreads();
    float* e2 = pp;                     // reuse pp[0..127]
    if (h == 0) e2[r] = ee[r] * ee[r];
    float gl_in = FLT_MAX, gu_in = -FLT_MAX;
    if (h == 0) {
        const float rad = fabsf(ee[r]) + ((r < 127) ? fabsf(ee[r + 1]) : 0.0f);
        gl_in = dd[r] - rad;
        gu_in = dd[r] + rad;
    }
    const float gl = brmin256(gl_in, red);
    const float gu = brmax256(gu_in, red);
    __syncthreads();

    const float pivmin = fmaxf(1e-12f * fmaxf(fabsf(gl), fabsf(gu)), 1e-36f);
    float v = 0.0f;
    if (h == 0) {
        float lo = gl, hi = gu;
        for (int iter = 0; iter < 36; ++iter) {
            const float mid = 0.5f * (lo + hi);
            int cnt = 0;
            float q = dd[0] - mid;
            if (q < 0.0f) cnt++;
#pragma unroll 4
            for (int i = 1; i < 128; i++) {
                if (fabsf(q) < pivmin) q = -pivmin;
                q = dd[i] - mid - __fdividef(e2[i], q);
                if (q < 0.0f) cnt++;
            }
            if (cnt > r) hi = mid; else lo = mid;
        }
        const float lam = 0.5f * (lo + hi);
        v = (lam > 0.0f) ? sqrtf(lam) : 0.0f;
    }
    const float s = brs256(v, red);
    if (t == 0) g_partial[b] = s;
}

// ---------------- K4: mean over batch ----------------
__global__ void finalize_kernel(float* out) {
    out[0] = 0.25f * (g_partial[0] + g_partial[1] + g_partial[2] + g_partial[3]);
}

// ---------------- launch ----------------
extern "C" void kernel_launch(void* const* d_in, const int* in_sizes, int n_in,
                              void* d_out, int out_size) {
    const float* x  = (const float*)d_in[0];
    const float* J  = (const float*)d_in[1];
    const int*   ei = (const int*)d_in[2];     // [2, E] int32, e0 sorted
    const int E = in_sizes[2] / 2;
    float* out = (float*)d_out;

    cudaFuncSetAttribute(eigen_kernel,
                         cudaFuncAttributeMaxDynamicSharedMemorySize, SMEM_EIG);

    rowptr_kernel<<<(N_NODES + 1 + 255) / 256, 256>>>(ei, E);

    dim3 gbuild(N_NODES / 2, BATCH);
    build_kernel<<<gbuild, 256>>>(x, J, ei + E);

    dim3 ggemm(KS, BATCH);
    gemm_kernel<<<ggemm, 256>>>(J);
    reduce_kernel<<<BATCH * D * D / 256, 256>>>();

    eigen_kernel<<<BATCH, 256, SMEM_EIG>>>();
    finalize_kernel<<<1, 1>>>(out);
}

// round 8
// speedup vs baseline: 1.0920x; 1.0920x over previous
#include <cuda_runtime.h>
#include <math.h>
#include <stdint.h>

#define N_NODES 16384
#define D 128
#define BATCH 4
#define WPRIME (0.05f/1.05f)
#define EMAX 98304               // >= actual E (97282)

#define KS 64                    // split-K factor
#define CHUNK (N_NODES / KS)     // 256 nodes per block
#define STAGES 4
#define SROW 136                 // smem row stride (floats), conflict-free fragments

// ---------------- device scratch (no allocations allowed) ----------------
__device__ float g_Rm[BATCH * D * D];
__device__ float g_Rp[(size_t)BATCH * KS * D * D];
__device__ int   g_rowptr[N_NODES + 1];
__device__ float g_partial[BATCH];
__device__ float g_pan[(size_t)BATCH * N_NODES * 1024];
__device__ float4 g_edgev[(size_t)BATCH * EMAX];
// per node 12 floats: deg, s0,s1,s2, il00,l10,il11,l20,l21,il22, wGinv, pad
__device__ float g_geo[(size_t)BATCH * N_NODES * 12];

// ---------------- K1: CSR row pointers (e0 sorted ascending) ----------------
__global__ void rowptr_kernel(const int* __restrict__ e0, int E) {
    int n = blockIdx.x * blockDim.x + threadIdx.x;
    if (n > N_NODES) return;
    int lo = 0, hi = E;
    while (lo < hi) {
        int mid = (lo + hi) >> 1;
        if (e0[mid] < n) lo = mid + 1; else hi = mid;
    }
    g_rowptr[n] = lo;
}

// ---------------- K1b: per-node geometry precompute (1 thread per node) ----------------
__global__ void geom_kernel(const float* __restrict__ x, const int* __restrict__ e1arr) {
    const int n = blockIdx.x * blockDim.x + threadIdx.x;
    const int b = blockIdx.y;
    if (n >= N_NODES) return;

    const float* xb = x + (size_t)b * N_NODES * 3;
    const float xn0 = xb[3 * n], xn1 = xb[3 * n + 1], xn2 = xb[3 * n + 2];
    float4* ev = g_edgev + (size_t)b * EMAX;

    float deg = 0.f, s0 = 0.f, s1 = 0.f, s2 = 0.f, G = 0.f;
    float c00 = 0.f, c01 = 0.f, c02 = 0.f, c11 = 0.f, c12 = 0.f, c22 = 0.f;

    const int eBeg = g_rowptr[n], eEnd = g_rowptr[n + 1];
    for (int e = eBeg; e < eEnd; ++e) {
        const int m = e1arr[e];
        const float v0 = xn0 - xb[3 * m];
        const float v1 = xn1 - xb[3 * m + 1];
        const float v2 = xn2 - xb[3 * m + 2];
        ev[e] = make_float4(v0, v1, v2, 0.0f);
        deg += 1.0f; s0 += v0; s1 += v1; s2 += v2;
        const float vv = v0 * v0 + v1 * v1 + v2 * v2;
        G += vv;
        c00 += vv - v0 * v0; c01 -= v0 * v1; c02 -= v0 * v2;
        c11 += vv - v1 * v1; c12 -= v1 * v2; c22 += vv - v2 * v2;
    }

    // Cholesky C = L L^T (store inverse-apply factors)
    const float l00 = sqrtf(c00);
    const float il00 = 1.0f / l00;
    const float l10 = c01 * il00, l20 = c02 * il00;
    const float l11 = sqrtf(c11 - l10 * l10);
    const float il11 = 1.0f / l11;
    const float l21 = (c12 - l20 * l10) * il11;
    const float l22 = sqrtf(c22 - l20 * l20 - l21 * l21);
    const float il22 = 1.0f / l22;
    const float Ginv = (G < 1e-6f) ? 0.0f : 1.0f / G;

    float* ge = g_geo + ((size_t)b * N_NODES + n) * 12;
    ge[0] = deg; ge[1] = s0; ge[2] = s1; ge[3] = s2;
    ge[4] = il00; ge[5] = l10; ge[6] = il11;
    ge[7] = l20; ge[8] = l21; ge[9] = il22;
    ge[10] = WPRIME * Ginv; ge[11] = 0.0f;
}

// ---------------- K2a: build per-node panels (J-gather only) ----------------
__global__ void __launch_bounds__(256)
build_kernel(const float* __restrict__ J, const int* __restrict__ e1arr) {
    const int b = blockIdx.y;
    const int n = blockIdx.x * 2 + (threadIdx.x >> 7);
    const int c = threadIdx.x & 127;

    const float* Jb = J + (size_t)b * N_NODES * 3 * D;
    const float4* ev = g_edgev + (size_t)b * EMAX;

    const float* Jn = Jb + (size_t)(3 * n) * D + c;
    const float Jn0 = Jn[0], Jn1 = Jn[D], Jn2 = Jn[2 * D];

    float nb0 = 0.f, nb1 = 0.f, nb2 = 0.f;
    float T0 = 0.f, T1 = 0.f, T2 = 0.f, u = 0.f;

    const int eBeg = g_rowptr[n], eEnd = g_rowptr[n + 1];
#pragma unroll 2
    for (int e = eBeg; e < eEnd; ++e) {
        const int m = e1arr[e];
        const float4 v = ev[e];
        const float* Jm = Jb + (size_t)(3 * m) * D + c;
        const float Jm0 = Jm[0], Jm1 = Jm[D], Jm2 = Jm[2 * D];
        nb0 += Jm0; nb1 += Jm1; nb2 += Jm2;
        T0 += v.y * Jm2 - v.z * Jm1;
        T1 += v.z * Jm0 - v.x * Jm2;
        T2 += v.x * Jm1 - v.y * Jm0;
        u  += v.x * Jm0 + v.y * Jm1 + v.z * Jm2;
    }

    const float* ge = g_geo + ((size_t)b * N_NODES + n) * 12;
    const float deg = ge[0], s0 = ge[1], s1 = ge[2], s2 = ge[3];
    const float il00 = ge[4], l10 = ge[5], il11 = ge[6];
    const float l20 = ge[7], l21 = ge[8], il22 = ge[9];
    const float wGinv = ge[10];

    const float LJ0 = 2.0f * (deg * Jn0 - nb0);
    const float LJ1 = 2.0f * (deg * Jn1 - nb1);
    const float LJ2 = 2.0f * (deg * Jn2 - nb2);
    const float B0 = T0 + s2 * Jn1 - s1 * Jn2;
    const float B1 = T1 - s2 * Jn0 + s0 * Jn2;
    const float B2 = T2 + s1 * Jn0 - s0 * Jn1;
    const float y = u - (s0 * Jn0 + s1 * Jn1 + s2 * Jn2);
    const float Z0 = B0 * il00;
    const float Z1 = (B1 - l10 * Z0) * il11;
    const float Z2 = (B2 - l20 * Z0 - l21 * Z1) * il22;

    float* P = g_pan + ((size_t)b * N_NODES + n) * 1024 + c;
    P[0*128] = Z0;   P[1*128] = Z1;   P[2*128] = Z2;   P[3*128] = y;
    P[4*128] = LJ0;  P[5*128] = LJ1;  P[6*128] = LJ2;
    P[7*128] = -wGinv * y;
}

// ---------------- K2b: TF32 tensor-core split-K GEMM (slim panels) ----------------
__device__ __forceinline__ void cp_async16(void* dst_smem, const void* src) {
    uint32_t d = (uint32_t)__cvta_generic_to_shared(dst_smem);
    asm volatile("cp.async.cg.shared.global [%0], [%1], 16;" :: "r"(d), "l"(src));
}
__device__ __forceinline__ void cp_commit() { asm volatile("cp.async.commit_group;"); }
template<int NN> __device__ __forceinline__ void cp_wait() {
    asm volatile("cp.async.wait_group %0;" :: "n"(NN));
}
__device__ __forceinline__ uint32_t tf32c(float f) {
    uint32_t u; asm("cvt.rna.tf32.f32 %0, %1;" : "=r"(u) : "f"(f)); return u;
}
__device__ __forceinline__ void mma_tf32(float* d, uint32_t a0, uint32_t a1,
                                         uint32_t a2, uint32_t a3,
                                         uint32_t b0, uint32_t b1) {
    asm volatile(
        "mma.sync.aligned.m16n8k8.row.col.f32.tf32.tf32.f32 "
        "{%0,%1,%2,%3}, {%4,%5,%6,%7}, {%8,%9}, {%0,%1,%2,%3};"
        : "+f"(d[0]), "+f"(d[1]), "+f"(d[2]), "+f"(d[3])
        : "r"(a0), "r"(a1), "r"(a2), "r"(a3), "r"(b0), "r"(b1));
}

__global__ void __launch_bounds__(256, 2)
gemm_kernel(const float* __restrict__ J) {
    __shared__ __align__(16) float sm[STAGES][12][SROW];

    const int b = blockIdx.y, ks = blockIdx.x;
    const int t = threadIdx.x;
    const int wid = t >> 5, lane = t & 31;
    const int wm = (wid >> 2) * 64;
    const int wn = (wid & 3) * 32;
    const int r0 = lane >> 2, kc = lane & 3;

    const int nodeBase = ks * CHUNK;
    const float* Jb = J + (size_t)b * N_NODES * 3 * D;
    const float* Pb = g_pan + ((size_t)b * N_NODES + nodeBase) * 1024;

    for (int idx = t; idx < STAGES * SROW; idx += 256)
        sm[idx / SROW][7][idx % SROW] = 0.0f;

    const int   brow0 = (kc < 3) ? 8 + kc : 3;
    const float bsgn0 = (kc < 3) ? 1.0f : -1.0f;
    const int   brow1 = (kc < 2) ? 4 + kc : ((kc == 2) ? 11 : 7);
    const float bsgn1 = (kc < 2) ? -1.0f : 1.0f;

    float acc[4][4][4];
#pragma unroll
    for (int i = 0; i < 4; i++)
#pragma unroll
        for (int j = 0; j < 4; j++)
#pragma unroll
            for (int r = 0; r < 4; r++) acc[i][j][r] = 0.0f;

    auto issue = [&](int it) {
        const int stg = it & (STAGES - 1);
        const float* psrc = Pb + (size_t)it * 1024;
        {
            const int prow = t >> 5;
            const int srow = (prow < 4) ? 3 + prow : 4 + prow;
            cp_async16(&sm[stg][srow][(t & 31) * 4], psrc + t * 4);
        }
        if (t < 96) {
            const float* jsrc = Jb + (size_t)(3 * (nodeBase + it)) * D;
            cp_async16(&sm[stg][t >> 5][(t & 31) * 4], jsrc + t * 4);
        }
    };

    for (int s = 0; s < STAGES - 1; s++) { issue(s); cp_commit(); }

    for (int it = 0; it < CHUNK; ++it) {
        const int stg = it & (STAGES - 1);
        if (it + STAGES - 1 < CHUNK) issue(it + STAGES - 1);
        cp_commit();
        cp_wait<STAGES - 1>();
        __syncthreads();

        const float* S = &sm[stg][0][0];

        uint32_t bb[4][2];
#pragma unroll
        for (int nt = 0; nt < 4; nt++) {
            const int n = wn + nt * 8 + r0;
            bb[nt][0] = tf32c(bsgn0 * S[brow0 * SROW + n]);
            bb[nt][1] = tf32c(bsgn1 * S[brow1 * SROW + n]);
        }
#pragma unroll
        for (int mt = 0; mt < 4; mt++) {
            const int m = wm + mt * 16 + r0;
            const uint32_t a0 = tf32c(S[kc * SROW + m]);
            const uint32_t a1 = tf32c(S[kc * SROW + m + 8]);
            const uint32_t a2 = tf32c(S[(kc + 4) * SROW + m]);
            const uint32_t a3 = tf32c(S[(kc + 4) * SROW + m + 8]);
#pragma unroll
            for (int nt = 0; nt < 4; nt++)
                mma_tf32(acc[mt][nt], a0, a1, a2, a3, bb[nt][0], bb[nt][1]);
        }
        __syncthreads();
    }

    float* out = g_Rp + (((size_t)b * KS + ks) << 14);
#pragma unroll
    for (int mt = 0; mt < 4; mt++) {
        const int m = wm + mt * 16 + r0;
#pragma unroll
        for (int nt = 0; nt < 4; nt++) {
            const int n = wn + nt * 8 + 2 * kc;
            *(float2*)&out[m * 128 + n]       = make_float2(acc[mt][nt][0], acc[mt][nt][1]);
            *(float2*)&out[(m + 8) * 128 + n] = make_float2(acc[mt][nt][2], acc[mt][nt][3]);
        }
    }
}

// ---------------- K2c: reduce split-K partials ----------------
__global__ void reduce_kernel() {
    const int idx = blockIdx.x * 256 + threadIdx.x;
    const int b = idx >> 14;
    const float* p = g_Rp + (((size_t)b * KS) << 14) + (idx & 16383);
    float s = 0.0f;
#pragma unroll 8
    for (int k = 0; k < KS; k++) s += p[(size_t)k << 14];
    g_Rm[idx] = s;
}

// ---------------- legacy 3-sync block reductions (eigen tail only) ----------------
__device__ __forceinline__ float blockReduceSum(float v, float* red) {
#pragma unroll
    for (int off = 16; off > 0; off >>= 1) v += __shfl_down_sync(0xffffffffu, v, off);
    if ((threadIdx.x & 31) == 0) red[threadIdx.x >> 5] = v;
    __syncthreads();
    if (threadIdx.x == 0) red[0] = red[0] + red[1] + red[2] + red[3];
    __syncthreads();
    const float r = red[0];
    __syncthreads();
    return r;
}
__device__ __forceinline__ float blockReduceMin(float v, float* red) {
#pragma unroll
    for (int off = 16; off > 0; off >>= 1) v = fminf(v, __shfl_down_sync(0xffffffffu, v, off));
    if ((threadIdx.x & 31) == 0) red[threadIdx.x >> 5] = v;
    __syncthreads();
    if (threadIdx.x == 0) red[0] = fminf(fminf(red[0], red[1]), fminf(red[2], red[3]));
    __syncthreads();
    const float r = red[0];
    __syncthreads();
    return r;
}
__device__ __forceinline__ float blockReduceMax(float v, float* red) {
#pragma unroll
    for (int off = 16; off > 0; off >>= 1) v = fmaxf(v, __shfl_down_sync(0xffffffffu, v, off));
    if ((threadIdx.x & 31) == 0) red[threadIdx.x >> 5] = v;
    __syncthreads();
    if (threadIdx.x == 0) red[0] = fmaxf(fmaxf(red[0], red[1]), fmaxf(red[2], red[3]));
    __syncthreads();
    const float r = red[0];
    __syncthreads();
    return r;
}

// ---------------- K3: Householder + Sturm, 128 threads, 5 barriers/iter ----------------
#define ASTR 132
#define SMEM_EIG ((128 * ASTR + 5 * 128 + 64) * 4)

__global__ void eigen_kernel() {
    extern __shared__ float smE[];
    float* A   = smE;                 // 128 x ASTR
    float* uu  = A + 128 * ASTR;      // 128
    float* qq  = uu + 128;            // 128
    float* dd  = qq + 128;            // 128
    float* ee  = dd + 128;            // 128
    float* e2  = ee + 128;            // 128
    float* red = e2 + 128;            // 64: [0..15] loop slots (parity x {sig,Ks}), [16..] tail

    const int b = blockIdx.x;
    const int t = threadIdx.x;
    const int w = t >> 5, lane = t & 31;
    const float* R = g_Rm + (size_t)b * D * D;

#pragma unroll 4
    for (int i = 0; i < 128; i++)
        A[i * ASTR + t] = 0.5f * (R[i * 128 + t] + R[t * 128 + i]);
    __syncthreads();

    for (int k = 0; k < 126; k++) {
        float* sA = red + (k & 1) * 8;       // slots 0..3
        float* sB = sA + 4;                  // slots 4..7
        const float xi = (t > k) ? A[t * ASTR + k] : 0.0f;
        // 1-sync reduction of xi^2
        float ws = xi * xi;
#pragma unroll
        for (int off = 16; off > 0; off >>= 1) ws += __shfl_down_sync(0xffffffffu, ws, off);
        if (lane == 0) sA[w] = ws;
        __syncthreads();                                   // (1)
        const float sig = (sA[0] + sA[1]) + (sA[2] + sA[3]);
        const float x0 = A[(k + 1) * ASTR + k];
        const float nrm = sqrtf(sig);
        const float alpha = (x0 >= 0.0f) ? -nrm : nrm;
        const float H = sig - alpha * x0;
        if (t == 0) ee[k + 1] = alpha;
        const float ui = (t > k) ? (xi - ((t == k + 1) ? alpha : 0.0f)) : 0.0f;
        uu[t] = ui;
        __syncthreads();                                   // (2)
        if (H > 1e-32f) {                                  // block-uniform branch
            const float invH = 1.0f / H;
            const int j0 = (k + 1) & ~3;
            const int m = (128 - j0) >> 2;
            float p = 0.0f;
            if (t > k) {
                const float4* Ar4 = (const float4*)(A + t * ASTR + j0);
                const float4* U4  = (const float4*)(uu + j0);
                float pa[4] = {0.f, 0.f, 0.f, 0.f};
#pragma unroll 4
                for (int q = 0; q < m; q++) {
                    const float4 a = Ar4[q], u4 = U4[q];
                    pa[q & 3] += a.x * u4.x + a.y * u4.y + a.z * u4.z + a.w * u4.w;
                }
                p = ((pa[0] + pa[1]) + (pa[2] + pa[3])) * invH;
            }
            // 1-sync reduction of ui*p
            float kv = ui * p;
#pragma unroll
            for (int off = 16; off > 0; off >>= 1) kv += __shfl_down_sync(0xffffffffu, kv, off);
            if (lane == 0) sB[w] = kv;
            __syncthreads();                               // (3)
            const float Ks = (sB[0] + sB[1]) + (sB[2] + sB[3]);
            const float Kc = Ks * 0.5f * invH;
            qq[t] = p - Kc * ui;
            __syncthreads();                               // (4)
            if (t > k) {
                float4* Ar4 = (float4*)(A + t * ASTR + j0);
                const float4* U4 = (const float4*)(uu + j0);
                const float4* Q4 = (const float4*)(qq + j0);
                const float uif = ui, qif = qq[t];
#pragma unroll 4
                for (int q = 0; q < m; q++) {
                    float4 a = Ar4[q];
                    const float4 u4 = U4[q], q4 = Q4[q];
                    a.x -= uif * q4.x + qif * u4.x;
                    a.y -= uif * q4.y + qif * u4.y;
                    a.z -= uif * q4.z + qif * u4.z;
                    a.w -= uif * q4.w + qif * u4.w;
                    Ar4[q] = a;
                }
            }
        }
        __syncthreads();                                   // (5)
    }

    dd[t] = A[t * ASTR + t];
    if (t == 0) { ee[0] = 0.0f; ee[127] = A[127 * ASTR + 126]; }
    __syncthreads();
    e2[t] = ee[t] * ee[t];
    const float rad = fabsf(ee[t]) + ((t < 127) ? fabsf(ee[t + 1]) : 0.0f);
    const float gl = blockReduceMin(dd[t] - rad, red + 16);
    const float gu = blockReduceMax(dd[t] + rad, red + 16);
    __syncthreads();

    const float pivmin = fmaxf(1e-12f * fmaxf(fabsf(gl), fabsf(gu)), 1e-36f);
    float lo = gl, hi = gu;
    for (int iter = 0; iter < 36; ++iter) {
        const float mid = 0.5f * (lo + hi);
        int cnt = 0;
        float q = dd[0] - mid;
        if (q < 0.0f) cnt++;
#pragma unroll 4
        for (int i = 1; i < 128; i++) {
            if (fabsf(q) < pivmin) q = -pivmin;
            q = dd[i] - mid - __fdividef(e2[i], q);
            if (q < 0.0f) cnt++;
        }
        if (cnt > t) hi = mid; else lo = mid;
    }
    const float lam = 0.5f * (lo + hi);
    const float v = (lam > 0.0f) ? sqrtf(lam) : 0.0f;
    const float s = blockReduceSum(v, red + 16);
    if (t == 0) g_partial[b] = s;
}

// ---------------- K4: mean over batch ----------------
__global__ void finalize_kernel(float* out) {
    out[0] = 0.25f * (g_partial[0] + g_partial[1] + g_partial[2] + g_partial[3]);
}

// ---------------- launch ----------------
extern "C" void kernel_launch(void* const* d_in, const int* in_sizes, int n_in,
                              void* d_out, int out_size) {
    const float* x  = (const float*)d_in[0];
    const float* J  = (const float*)d_in[1];
    const int*   ei = (const int*)d_in[2];     // [2, E] int32, e0 sorted
    const int E = in_sizes[2] / 2;
    float* out = (float*)d_out;

    cudaFuncSetAttribute(eigen_kernel,
                         cudaFuncAttributeMaxDynamicSharedMemorySize, SMEM_EIG);

    rowptr_kernel<<<(N_NODES + 1 + 255) / 256, 256>>>(ei, E);

    dim3 ggeo((N_NODES + 127) / 128, BATCH);
    geom_kernel<<<ggeo, 128>>>(x, ei + E);

    dim3 gbuild(N_NODES / 2, BATCH);
    build_kernel<<<gbuild, 256>>>(J, ei + E);

    dim3 ggemm(KS, BATCH);
    gemm_kernel<<<ggemm, 256>>>(J);
    reduce_kernel<<<BATCH * D * D / 256, 256>>>();

    eigen_kernel<<<BATCH, 128, SMEM_EIG>>>();
    finalize_kernel<<<1, 1>>>(out);
}

// round 9
// speedup vs baseline: 1.1645x; 1.0664x over previous
#include <cuda_runtime.h>
#include <math.h>
#include <stdint.h>

#define N_NODES 16384
#define D 128
#define BATCH 4
#define WPRIME (0.05f/1.05f)
#define EMAX 98304

#define KS 64
#define CHUNK (N_NODES / KS)     // 256 nodes per block
#define NIT (CHUNK / 2)          // 128 iterations, 2 nodes each
#define STAGES 4
#define SROW 136
#define STAGE_F (24 * SROW)      // floats per stage (2 nodes x 12 rows)
#define GSMEM (STAGES * STAGE_F * 4)

// ---------------- device scratch ----------------
__device__ float g_Rm[BATCH * D * D];
__device__ float g_Rp[(size_t)BATCH * KS * D * D];
__device__ int   g_rowptr[N_NODES + 1];
__device__ float g_partial[BATCH];
__device__ float g_pan[(size_t)BATCH * N_NODES * 1024];
__device__ float4 g_edgev[(size_t)BATCH * EMAX];
__device__ float g_geo[(size_t)BATCH * N_NODES * 12];

__device__ __forceinline__ uint32_t tf32c(float f) {
    uint32_t u; asm("cvt.rna.tf32.f32 %0, %1;" : "=r"(u) : "f"(f)); return u;
}
__device__ __forceinline__ float tf32f(float f) {
    return __uint_as_float(tf32c(f));
}

// ---------------- K1: CSR row pointers ----------------
__global__ void rowptr_kernel(const int* __restrict__ e0, int E) {
    int n = blockIdx.x * blockDim.x + threadIdx.x;
    if (n > N_NODES) return;
    int lo = 0, hi = E;
    while (lo < hi) {
        int mid = (lo + hi) >> 1;
        if (e0[mid] < n) lo = mid + 1; else hi = mid;
    }
    g_rowptr[n] = lo;
}

// ---------------- K1b: per-node geometry ----------------
__global__ void geom_kernel(const float* __restrict__ x, const int* __restrict__ e1arr) {
    const int n = blockIdx.x * blockDim.x + threadIdx.x;
    const int b = blockIdx.y;
    if (n >= N_NODES) return;

    const float* xb = x + (size_t)b * N_NODES * 3;
    const float xn0 = xb[3 * n], xn1 = xb[3 * n + 1], xn2 = xb[3 * n + 2];
    float4* ev = g_edgev + (size_t)b * EMAX;

    float deg = 0.f, s0 = 0.f, s1 = 0.f, s2 = 0.f, G = 0.f;
    float c00 = 0.f, c01 = 0.f, c02 = 0.f, c11 = 0.f, c12 = 0.f, c22 = 0.f;

    const int eBeg = g_rowptr[n], eEnd = g_rowptr[n + 1];
    for (int e = eBeg; e < eEnd; ++e) {
        const int m = e1arr[e];
        const float v0 = xn0 - xb[3 * m];
        const float v1 = xn1 - xb[3 * m + 1];
        const float v2 = xn2 - xb[3 * m + 2];
        ev[e] = make_float4(v0, v1, v2, 0.0f);
        deg += 1.0f; s0 += v0; s1 += v1; s2 += v2;
        const float vv = v0 * v0 + v1 * v1 + v2 * v2;
        G += vv;
        c00 += vv - v0 * v0; c01 -= v0 * v1; c02 -= v0 * v2;
        c11 += vv - v1 * v1; c12 -= v1 * v2; c22 += vv - v2 * v2;
    }

    const float l00 = sqrtf(c00);
    const float il00 = 1.0f / l00;
    const float l10 = c01 * il00, l20 = c02 * il00;
    const float l11 = sqrtf(c11 - l10 * l10);
    const float il11 = 1.0f / l11;
    const float l21 = (c12 - l20 * l10) * il11;
    const float l22 = sqrtf(c22 - l20 * l20 - l21 * l21);
    const float il22 = 1.0f / l22;
    const float Ginv = (G < 1e-6f) ? 0.0f : 1.0f / G;

    float* ge = g_geo + ((size_t)b * N_NODES + n) * 12;
    ge[0] = deg; ge[1] = s0; ge[2] = s1; ge[3] = s2;
    ge[4] = il00; ge[5] = l10; ge[6] = il11;
    ge[7] = l20; ge[8] = l21; ge[9] = il22;
    ge[10] = WPRIME * Ginv; ge[11] = 0.0f;
}

// ---------------- K2a: build panels (writes pre-rounded TF32 bits) ----------------
__global__ void __launch_bounds__(256)
build_kernel(const float* __restrict__ J, const int* __restrict__ e1arr) {
    const int b = blockIdx.y;
    const int n = blockIdx.x * 2 + (threadIdx.x >> 7);
    const int c = threadIdx.x & 127;

    const float* Jb = J + (size_t)b * N_NODES * 3 * D;
    const float4* ev = g_edgev + (size_t)b * EMAX;

    const float* Jn = Jb + (size_t)(3 * n) * D + c;
    const float Jn0 = Jn[0], Jn1 = Jn[D], Jn2 = Jn[2 * D];

    float nb0 = 0.f, nb1 = 0.f, nb2 = 0.f;
    float T0 = 0.f, T1 = 0.f, T2 = 0.f, u = 0.f;

    const int eBeg = g_rowptr[n], eEnd = g_rowptr[n + 1];
#pragma unroll 2
    for (int e = eBeg; e < eEnd; ++e) {
        const int m = e1arr[e];
        const float4 v = ev[e];
        const float* Jm = Jb + (size_t)(3 * m) * D + c;
        const float Jm0 = Jm[0], Jm1 = Jm[D], Jm2 = Jm[2 * D];
        nb0 += Jm0; nb1 += Jm1; nb2 += Jm2;
        T0 += v.y * Jm2 - v.z * Jm1;
        T1 += v.z * Jm0 - v.x * Jm2;
        T2 += v.x * Jm1 - v.y * Jm0;
        u  += v.x * Jm0 + v.y * Jm1 + v.z * Jm2;
    }

    const float* ge = g_geo + ((size_t)b * N_NODES + n) * 12;
    const float deg = ge[0], s0 = ge[1], s1 = ge[2], s2 = ge[3];
    const float il00 = ge[4], l10 = ge[5], il11 = ge[6];
    const float l20 = ge[7], l21 = ge[8], il22 = ge[9];
    const float wGinv = ge[10];

    const float LJ0 = 2.0f * (deg * Jn0 - nb0);
    const float LJ1 = 2.0f * (deg * Jn1 - nb1);
    const float LJ2 = 2.0f * (deg * Jn2 - nb2);
    const float B0 = T0 + s2 * Jn1 - s1 * Jn2;
    const float B1 = T1 - s2 * Jn0 + s0 * Jn2;
    const float B2 = T2 + s1 * Jn0 - s0 * Jn1;
    const float y = u - (s0 * Jn0 + s1 * Jn1 + s2 * Jn2);
    const float Z0 = B0 * il00;
    const float Z1 = (B1 - l10 * Z0) * il11;
    const float Z2 = (B2 - l20 * Z0 - l21 * Z1) * il22;

    float* P = g_pan + ((size_t)b * N_NODES + n) * 1024 + c;
    P[0*128] = tf32f(Z0);   P[1*128] = tf32f(Z1);   P[2*128] = tf32f(Z2);
    P[3*128] = tf32f(y);
    P[4*128] = tf32f(LJ0);  P[5*128] = tf32f(LJ1);  P[6*128] = tf32f(LJ2);
    P[7*128] = tf32f(-wGinv * y);
}

// ---------------- K2b: TF32 split-K GEMM, 2 nodes per stage ----------------
// per-node 12 smem rows: 0:J0 1:J1 2:J2 3:Z0 4:Z1 5:Z2 6:y 7:ZERO 8:LJ0 9:LJ1 10:LJ2 11:gy
__device__ __forceinline__ void cp_async16(void* dst_smem, const void* src) {
    uint32_t d = (uint32_t)__cvta_generic_to_shared(dst_smem);
    asm volatile("cp.async.cg.shared.global [%0], [%1], 16;" :: "r"(d), "l"(src));
}
__device__ __forceinline__ void cp_commit() { asm volatile("cp.async.commit_group;"); }
template<int NN> __device__ __forceinline__ void cp_wait() {
    asm volatile("cp.async.wait_group %0;" :: "n"(NN));
}
__device__ __forceinline__ void mma_tf32(float* d, uint32_t a0, uint32_t a1,
                                         uint32_t a2, uint32_t a3,
                                         uint32_t b0, uint32_t b1) {
    asm volatile(
        "mma.sync.aligned.m16n8k8.row.col.f32.tf32.tf32.f32 "
        "{%0,%1,%2,%3}, {%4,%5,%6,%7}, {%8,%9}, {%0,%1,%2,%3};"
        : "+f"(d[0]), "+f"(d[1]), "+f"(d[2]), "+f"(d[3])
        : "r"(a0), "r"(a1), "r"(a2), "r"(a3), "r"(b0), "r"(b1));
}

__global__ void __launch_bounds__(256, 2)
gemm_kernel(const float* __restrict__ J) {
    extern __shared__ float smg[];   // [STAGES][24][SROW]

    const int b = blockIdx.y, ks = blockIdx.x;
    const int t = threadIdx.x;
    const int wid = t >> 5, lane = t & 31;
    const int wm = (wid >> 2) * 64;
    const int wn = (wid & 3) * 32;
    const int r0 = lane >> 2, kc = lane & 3;

    const int nodeBase = ks * CHUNK;
    const float* Jb = J + (size_t)b * N_NODES * 3 * D;
    const float* Pb = g_pan + ((size_t)b * N_NODES + nodeBase) * 1024;

    // zero rows 7 and 19 of every stage
    for (int idx = t; idx < STAGES * 2 * SROW; idx += 256) {
        const int s = idx / (2 * SROW);
        const int rem = idx - s * 2 * SROW;
        const int row = (rem < SROW) ? 7 : 19;
        smg[s * STAGE_F + row * SROW + (rem % SROW)] = 0.0f;
    }

    // per-lane B row LUT + sign masks (within a node's 12-row window)
    const int      brow0 = (kc < 3) ? 8 + kc : 3;
    const uint32_t bmsk0 = (kc < 3) ? 0u : 0x80000000u;
    const int      brow1 = (kc < 2) ? 4 + kc : ((kc == 2) ? 11 : 7);
    const uint32_t bmsk1 = (kc < 2) ? 0x80000000u : 0u;

    float acc[4][4][4];
#pragma unroll
    for (int i = 0; i < 4; i++)
#pragma unroll
        for (int j = 0; j < 4; j++)
#pragma unroll
            for (int r = 0; r < 4; r++) acc[i][j][r] = 0.0f;

    const int prow = t >> 5;
    const int scol = (t & 31) * 4;
    const int srowP = (prow < 4) ? 3 + prow : 4 + prow;   // panel rows 3..6, 8..11

    auto issue = [&](int it) {
        const int stg = it & (STAGES - 1);
        float* SB = smg + stg * STAGE_F;
        const float* p0 = Pb + (size_t)(2 * it) * 1024;
        cp_async16(SB + srowP * SROW + scol, p0 + t * 4);
        cp_async16(SB + (12 + srowP) * SROW + scol, p0 + 1024 + t * 4);
        if (t < 96) {
            const float* j0 = Jb + (size_t)(3 * (nodeBase + 2 * it)) * D;
            cp_async16(SB + prow * SROW + scol, j0 + t * 4);
            cp_async16(SB + (12 + prow) * SROW + scol, j0 + 384 + t * 4);
        }
    };

    for (int s = 0; s < STAGES - 1; s++) { issue(s); cp_commit(); }

    for (int it = 0; it < NIT; ++it) {
        const int stg = it & (STAGES - 1);
        if (it + STAGES - 1 < NIT) issue(it + STAGES - 1);
        cp_commit();
        cp_wait<STAGES - 1>();
        __syncthreads();

        const float* S0 = smg + stg * STAGE_F;
#pragma unroll
        for (int g = 0; g < 2; ++g) {
            const float* S = S0 + g * 12 * SROW;

            uint32_t bb[4][2];
#pragma unroll
            for (int nt = 0; nt < 4; nt++) {
                const int n = wn + nt * 8 + r0;
                bb[nt][0] = __float_as_uint(S[brow0 * SROW + n]) ^ bmsk0;
                bb[nt][1] = __float_as_uint(S[brow1 * SROW + n]) ^ bmsk1;
            }
#pragma unroll
            for (int mt = 0; mt < 4; mt++) {
                const int m = wm + mt * 16 + r0;
                const uint32_t a0 = tf32c(S[kc * SROW + m]);       // idempotent on panel rows
                const uint32_t a1 = tf32c(S[kc * SROW + m + 8]);
                const uint32_t a2 = __float_as_uint(S[(kc + 4) * SROW + m]);
                const uint32_t a3 = __float_as_uint(S[(kc + 4) * SROW + m + 8]);
#pragma unroll
                for (int nt = 0; nt < 4; nt++)
                    mma_tf32(acc[mt][nt], a0, a1, a2, a3, bb[nt][0], bb[nt][1]);
            }
        }
        __syncthreads();
    }

    float* out = g_Rp + (((size_t)b * KS + ks) << 14);
#pragma unroll
    for (int mt = 0; mt < 4; mt++) {
        const int m = wm + mt * 16 + r0;
#pragma unroll
        for (int nt = 0; nt < 4; nt++) {
            const int n = wn + nt * 8 + 2 * kc;
            *(float2*)&out[m * 128 + n]       = make_float2(acc[mt][nt][0], acc[mt][nt][1]);
            *(float2*)&out[(m + 8) * 128 + n] = make_float2(acc[mt][nt][2], acc[mt][nt][3]);
        }
    }
}

// ---------------- K2c: reduce split-K partials ----------------
__global__ void reduce_kernel() {
    const int idx = blockIdx.x * 256 + threadIdx.x;
    const int b = idx >> 14;
    const float* p = g_Rp + (((size_t)b * KS) << 14) + (idx & 16383);
    float s = 0.0f;
#pragma unroll 8
    for (int k = 0; k < KS; k++) s += p[(size_t)k << 14];
    g_Rm[idx] = s;
}

// ---------------- legacy 3-sync block reductions (eigen tail only) ----------------
__device__ __forceinline__ float blockReduceSum(float v, float* red) {
#pragma unroll
    for (int off = 16; off > 0; off >>= 1) v += __shfl_down_sync(0xffffffffu, v, off);
    if ((threadIdx.x & 31) == 0) red[threadIdx.x >> 5] = v;
    __syncthreads();
    if (threadIdx.x == 0) red[0] = red[0] + red[1] + red[2] + red[3];
    __syncthreads();
    const float r = red[0];
    __syncthreads();
    return r;
}
__device__ __forceinline__ float blockReduceMin(float v, float* red) {
#pragma unroll
    for (int off = 16; off > 0; off >>= 1) v = fminf(v, __shfl_down_sync(0xffffffffu, v, off));
    if ((threadIdx.x & 31) == 0) red[threadIdx.x >> 5] = v;
    __syncthreads();
    if (threadIdx.x == 0) red[0] = fminf(fminf(red[0], red[1]), fminf(red[2], red[3]));
    __syncthreads();
    const float r = red[0];
    __syncthreads();
    return r;
}
__device__ __forceinline__ float blockReduceMax(float v, float* red) {
#pragma unroll
    for (int off = 16; off > 0; off >>= 1) v = fmaxf(v, __shfl_down_sync(0xffffffffu, v, off));
    if ((threadIdx.x & 31) == 0) red[threadIdx.x >> 5] = v;
    __syncthreads();
    if (threadIdx.x == 0) red[0] = fmaxf(fmaxf(red[0], red[1]), fmaxf(red[2], red[3]));
    __syncthreads();
    const float r = red[0];
    __syncthreads();
    return r;
}

// ---------------- K3: Householder (4 barriers/iter) + twisted-Sturm bisection ----------------
#define ASTR 132
#define SMEM_EIG ((128 * ASTR + 5 * 128 + 64) * 4)

__global__ void eigen_kernel() {
    extern __shared__ float smE[];
    float* A   = smE;                 // 128 x ASTR
    float* uu  = A + 128 * ASTR;      // 128  (holds x = col k below diag)
    float* qq  = uu + 128;            // 128
    float* dd  = qq + 128;            // 128
    float* ee  = dd + 128;            // 128
    float* e2  = ee + 128;            // 128
    float* red = e2 + 128;            // 64

    const int b = blockIdx.x;
    const int t = threadIdx.x;
    const int w = t >> 5, lane = t & 31;
    const float* R = g_Rm + (size_t)b * D * D;

#pragma unroll 4
    for (int i = 0; i < 128; i++)
        A[i * ASTR + t] = 0.5f * (R[i * 128 + t] + R[t * 128 + i]);
    __syncthreads();

    for (int k = 0; k < 126; k++) {
        float* sA = red + (k & 1) * 8;
        float* sB = sA + 4;
        const float xi = (t > k) ? A[t * ASTR + k] : 0.0f;
        uu[t] = xi;                                       // x vector (no alpha yet)
        float ws = xi * xi;
#pragma unroll
        for (int off = 16; off > 0; off >>= 1) ws += __shfl_down_sync(0xffffffffu, ws, off);
        if (lane == 0) sA[w] = ws;
        __syncthreads();                                  // (1) publishes uu + sA
        const float sig = (sA[0] + sA[1]) + (sA[2] + sA[3]);
        const float x0 = A[(k + 1) * ASTR + k];
        const float nrm = sqrtf(sig);
        const float alpha = (x0 >= 0.0f) ? -nrm : nrm;
        const float H = sig - alpha * x0;
        if (t == 0) ee[k + 1] = alpha;
        const float ut = xi - ((t == k + 1) ? alpha : 0.0f);   // true u_t, register only
        if (H > 1e-32f) {
            const float invH = 1.0f / H;
            const int j0 = (k + 1) & ~3;
            const int m = (128 - j0) >> 2;
            float p = 0.0f;
            if (t > k) {
                const float4* Ar4 = (const float4*)(A + t * ASTR + j0);
                const float4* U4  = (const float4*)(uu + j0);
                float pa[4] = {0.f, 0.f, 0.f, 0.f};
#pragma unroll 4
                for (int q = 0; q < m; q++) {
                    const float4 a = Ar4[q], u4 = U4[q];
                    pa[q & 3] += a.x * u4.x + a.y * u4.y + a.z * u4.z + a.w * u4.w;
                }
                // p = (A x - alpha * A(:,k+1))_t / H  == (A u)_t / H
                p = (((pa[0] + pa[1]) + (pa[2] + pa[3])) - alpha * A[t * ASTR + (k + 1)]) * invH;
            }
            float kv = ut * p;
#pragma unroll
            for (int off = 16; off > 0; off >>= 1) kv += __shfl_down_sync(0xffffffffu, kv, off);
            if (lane == 0) sB[w] = kv;
            __syncthreads();                              // (2)
            const float Ks = (sB[0] + sB[1]) + (sB[2] + sB[3]);
            const float Kc = Ks * 0.5f * invH;
            const float qt = p - Kc * ut;
            qq[t] = qt;
            __syncthreads();                              // (3)
            if (t > k) {
                float4* Ar4 = (float4*)(A + t * ASTR + j0);
                const float4* U4 = (const float4*)(uu + j0);
                const float4* Q4 = (const float4*)(qq + j0);
#pragma unroll 4
                for (int q = 0; q < m; q++) {
                    float4 a = Ar4[q];
                    const float4 u4 = U4[q], q4 = Q4[q];
                    a.x -= ut * q4.x + qt * u4.x;
                    a.y -= ut * q4.y + qt * u4.y;
                    a.z -= ut * q4.z + qt * u4.z;
                    a.w -= ut * q4.w + qt * u4.w;
                    Ar4[q] = a;
                }
                // uu held x, not u: fix the j=k+1 term ( -= qt*(x-u) = -= qt*alpha )
                A[t * ASTR + (k + 1)] += alpha * qt;
            }
        }
        __syncthreads();                                  // (4)
    }

    dd[t] = A[t * ASTR + t];
    if (t == 0) { ee[0] = 0.0f; ee[127] = A[127 * ASTR + 126]; }
    __syncthreads();
    e2[t] = ee[t] * ee[t];
    const float rad = fabsf(ee[t]) + ((t < 127) ? fabsf(ee[t + 1]) : 0.0f);
    const float gl = blockReduceMin(dd[t] - rad, red + 16);
    const float gu = blockReduceMax(dd[t] + rad, red + 16);
    __syncthreads();

    // twisted-factorization Sturm count: forward chain rows 0..63,
    // backward chain rows 127..65, gamma at twist row 64 (Sylvester inertia).
    const float pivmin = fmaxf(1e-12f * fmaxf(fabsf(gl), fabsf(gu)), 1e-36f);
    float lo = gl, hi = gu;
    for (int iter = 0; iter < 30; ++iter) {
        const float mid = 0.5f * (lo + hi);
        int cnt = 0;
        float qf = dd[0] - mid;
        cnt += (qf < 0.0f);
        float qb = dd[127] - mid;
        cnt += (qb < 0.0f);
#pragma unroll 3
        for (int j = 1; j <= 63; j++) {
            if (fabsf(qf) < pivmin) qf = -pivmin;
            qf = dd[j] - mid - __fdividef(e2[j], qf);
            cnt += (qf < 0.0f);
            if (j <= 62) {
                const int i = 127 - j;                   // 126 .. 65
                if (fabsf(qb) < pivmin) qb = -pivmin;
                qb = dd[i] - mid - __fdividef(e2[i + 1], qb);
                cnt += (qb < 0.0f);
            }
        }
        if (fabsf(qf) < pivmin) qf = -pivmin;
        if (fabsf(qb) < pivmin) qb = -pivmin;
        const float gam = dd[64] - mid - __fdividef(e2[64], qf) - __fdividef(e2[65], qb);
        cnt += (gam < 0.0f);
        if (cnt > t) hi = mid; else lo = mid;
    }
    const float lam = 0.5f * (lo + hi);
    const float v = (lam > 0.0f) ? sqrtf(lam) : 0.0f;
    const float s = blockReduceSum(v, red + 16);
    if (t == 0) g_partial[b] = s;
}

// ---------------- K4: mean over batch ----------------
__global__ void finalize_kernel(float* out) {
    out[0] = 0.25f * (g_partial[0] + g_partial[1] + g_partial[2] + g_partial[3]);
}

// ---------------- launch ----------------
extern "C" void kernel_launch(void* const* d_in, const int* in_sizes, int n_in,
                              void* d_out, int out_size) {
    const float* x  = (const float*)d_in[0];
    const float* J  = (const float*)d_in[1];
    const int*   ei = (const int*)d_in[2];
    const int E = in_sizes[2] / 2;
    float* out = (float*)d_out;

    cudaFuncSetAttribute(eigen_kernel,
                         cudaFuncAttributeMaxDynamicSharedMemorySize, SMEM_EIG);
    cudaFuncSetAttribute(gemm_kernel,
                         cudaFuncAttributeMaxDynamicSharedMemorySize, GSMEM);

    rowptr_kernel<<<(N_NODES + 1 + 255) / 256, 256>>>(ei, E);

    dim3 ggeo((N_NODES + 127) / 128, BATCH);
    geom_kernel<<<ggeo, 128>>>(x, ei + E);

    dim3 gbuild(N_NODES / 2, BATCH);
    build_kernel<<<gbuild, 256>>>(J, ei + E);

    dim3 ggemm(KS, BATCH);
    gemm_kernel<<<ggemm, 256, GSMEM>>>(J);
    reduce_kernel<<<BATCH * D * D / 256, 256>>>();

    eigen_kernel<<<BATCH, 128, SMEM_EIG>>>();
    finalize_kernel<<<1, 1>>>(out);
}

// round 10
// speedup vs baseline: 1.3102x; 1.1251x over previous
#include <cuda_runtime.h>
#include <math.h>
#include <stdint.h>

#define N_NODES 16384
#define D 128
#define BATCH 4
#define WPRIME (0.05f/1.05f)
#define EMAX 98304

#define KS 74
#define PAIRS (N_NODES / 2)      // 8192 node pairs
#define STAGES 4
#define SROW 136
#define STAGE_F (24 * SROW)
#define GSMEM (STAGES * STAGE_F * 4)

// ---------------- device scratch ----------------
__device__ float g_Rm[BATCH * D * D];
__device__ float g_Rp[(size_t)BATCH * KS * D * D];
__device__ int   g_rowptr[N_NODES + 1];
__device__ float g_partial[BATCH];
__device__ float g_pan[(size_t)BATCH * N_NODES * 1024];
__device__ float4 g_edgev[(size_t)BATCH * EMAX];
__device__ float g_geo[(size_t)BATCH * N_NODES * 12];

__device__ __forceinline__ uint32_t tf32c(float f) {
    uint32_t u; asm("cvt.rna.tf32.f32 %0, %1;" : "=r"(u) : "f"(f)); return u;
}
__device__ __forceinline__ float tf32f(float f) {
    return __uint_as_float(tf32c(f));
}

// ---------------- K1: CSR row pointers ----------------
__global__ void rowptr_kernel(const int* __restrict__ e0, int E) {
    int n = blockIdx.x * blockDim.x + threadIdx.x;
    if (n > N_NODES) return;
    int lo = 0, hi = E;
    while (lo < hi) {
        int mid = (lo + hi) >> 1;
        if (e0[mid] < n) lo = mid + 1; else hi = mid;
    }
    g_rowptr[n] = lo;
}

// ---------------- K1b: per-node geometry ----------------
__global__ void geom_kernel(const float* __restrict__ x, const int* __restrict__ e1arr) {
    const int n = blockIdx.x * blockDim.x + threadIdx.x;
    const int b = blockIdx.y;
    if (n >= N_NODES) return;

    const float* xb = x + (size_t)b * N_NODES * 3;
    const float xn0 = xb[3 * n], xn1 = xb[3 * n + 1], xn2 = xb[3 * n + 2];
    float4* ev = g_edgev + (size_t)b * EMAX;

    float deg = 0.f, s0 = 0.f, s1 = 0.f, s2 = 0.f, G = 0.f;
    float c00 = 0.f, c01 = 0.f, c02 = 0.f, c11 = 0.f, c12 = 0.f, c22 = 0.f;

    const int eBeg = g_rowptr[n], eEnd = g_rowptr[n + 1];
    for (int e = eBeg; e < eEnd; ++e) {
        const int m = e1arr[e];
        const float v0 = xn0 - xb[3 * m];
        const float v1 = xn1 - xb[3 * m + 1];
        const float v2 = xn2 - xb[3 * m + 2];
        ev[e] = make_float4(v0, v1, v2, 0.0f);
        deg += 1.0f; s0 += v0; s1 += v1; s2 += v2;
        const float vv = v0 * v0 + v1 * v1 + v2 * v2;
        G += vv;
        c00 += vv - v0 * v0; c01 -= v0 * v1; c02 -= v0 * v2;
        c11 += vv - v1 * v1; c12 -= v1 * v2; c22 += vv - v2 * v2;
    }

    const float l00 = sqrtf(c00);
    const float il00 = 1.0f / l00;
    const float l10 = c01 * il00, l20 = c02 * il00;
    const float l11 = sqrtf(c11 - l10 * l10);
    const float il11 = 1.0f / l11;
    const float l21 = (c12 - l20 * l10) * il11;
    const float l22 = sqrtf(c22 - l20 * l20 - l21 * l21);
    const float il22 = 1.0f / l22;
    const float Ginv = (G < 1e-6f) ? 0.0f : 1.0f / G;

    float* ge = g_geo + ((size_t)b * N_NODES + n) * 12;
    ge[0] = deg; ge[1] = s0; ge[2] = s1; ge[3] = s2;
    ge[4] = il00; ge[5] = l10; ge[6] = il11;
    ge[7] = l20; ge[8] = l21; ge[9] = il22;
    ge[10] = WPRIME * Ginv; ge[11] = 0.0f;
}

// ---------------- K2a: build panels (pre-rounded TF32 bits) ----------------
__global__ void __launch_bounds__(256)
build_kernel(const float* __restrict__ J, const int* __restrict__ e1arr) {
    const int b = blockIdx.y;
    const int n = blockIdx.x * 2 + (threadIdx.x >> 7);
    const int c = threadIdx.x & 127;

    const float* Jb = J + (size_t)b * N_NODES * 3 * D;
    const float4* ev = g_edgev + (size_t)b * EMAX;

    const float* Jn = Jb + (size_t)(3 * n) * D + c;
    const float Jn0 = Jn[0], Jn1 = Jn[D], Jn2 = Jn[2 * D];

    float nb0 = 0.f, nb1 = 0.f, nb2 = 0.f;
    float T0 = 0.f, T1 = 0.f, T2 = 0.f, u = 0.f;

    const int eBeg = g_rowptr[n], eEnd = g_rowptr[n + 1];
#pragma unroll 2
    for (int e = eBeg; e < eEnd; ++e) {
        const int m = e1arr[e];
        const float4 v = ev[e];
        const float* Jm = Jb + (size_t)(3 * m) * D + c;
        const float Jm0 = Jm[0], Jm1 = Jm[D], Jm2 = Jm[2 * D];
        nb0 += Jm0; nb1 += Jm1; nb2 += Jm2;
        T0 += v.y * Jm2 - v.z * Jm1;
        T1 += v.z * Jm0 - v.x * Jm2;
        T2 += v.x * Jm1 - v.y * Jm0;
        u  += v.x * Jm0 + v.y * Jm1 + v.z * Jm2;
    }

    const float* ge = g_geo + ((size_t)b * N_NODES + n) * 12;
    const float deg = ge[0], s0 = ge[1], s1 = ge[2], s2 = ge[3];
    const float il00 = ge[4], l10 = ge[5], il11 = ge[6];
    const float l20 = ge[7], l21 = ge[8], il22 = ge[9];
    const float wGinv = ge[10];

    const float LJ0 = 2.0f * (deg * Jn0 - nb0);
    const float LJ1 = 2.0f * (deg * Jn1 - nb1);
    const float LJ2 = 2.0f * (deg * Jn2 - nb2);
    const float B0 = T0 + s2 * Jn1 - s1 * Jn2;
    const float B1 = T1 - s2 * Jn0 + s0 * Jn2;
    const float B2 = T2 + s1 * Jn0 - s0 * Jn1;
    const float y = u - (s0 * Jn0 + s1 * Jn1 + s2 * Jn2);
    const float Z0 = B0 * il00;
    const float Z1 = (B1 - l10 * Z0) * il11;
    const float Z2 = (B2 - l20 * Z0 - l21 * Z1) * il22;

    float* P = g_pan + ((size_t)b * N_NODES + n) * 1024 + c;
    P[0*128] = tf32f(Z0);   P[1*128] = tf32f(Z1);   P[2*128] = tf32f(Z2);
    P[3*128] = tf32f(y);
    P[4*128] = tf32f(LJ0);  P[5*128] = tf32f(LJ1);  P[6*128] = tf32f(LJ2);
    P[7*128] = tf32f(-wGinv * y);
}

// ---------------- K2b: TF32 split-K GEMM, 2 nodes/stage, KS=74 ----------------
__device__ __forceinline__ void cp_async16(void* dst_smem, const void* src) {
    uint32_t d = (uint32_t)__cvta_generic_to_shared(dst_smem);
    asm volatile("cp.async.cg.shared.global [%0], [%1], 16;" :: "r"(d), "l"(src));
}
__device__ __forceinline__ void cp_commit() { asm volatile("cp.async.commit_group;"); }
template<int NN> __device__ __forceinline__ void cp_wait() {
    asm volatile("cp.async.wait_group %0;" :: "n"(NN));
}
__device__ __forceinline__ void mma_tf32(float* d, uint32_t a0, uint32_t a1,
                                         uint32_t a2, uint32_t a3,
                                         uint32_t b0, uint32_t b1) {
    asm volatile(
        "mma.sync.aligned.m16n8k8.row.col.f32.tf32.tf32.f32 "
        "{%0,%1,%2,%3}, {%4,%5,%6,%7}, {%8,%9}, {%0,%1,%2,%3};"
        : "+f"(d[0]), "+f"(d[1]), "+f"(d[2]), "+f"(d[3])
        : "r"(a0), "r"(a1), "r"(a2), "r"(a3), "r"(b0), "r"(b1));
}

__global__ void __launch_bounds__(256, 2)
gemm_kernel(const float* __restrict__ J) {
    extern __shared__ float smg[];   // [STAGES][24][SROW]

    const int b = blockIdx.y, ks = blockIdx.x;
    const int t = threadIdx.x;
    const int wid = t >> 5, lane = t & 31;
    const int wm = (wid >> 2) * 64;
    const int wn = (wid & 3) * 32;
    const int r0 = lane >> 2, kc = lane & 3;

    const int pbeg = (ks * PAIRS) / KS;
    const int pend = ((ks + 1) * PAIRS) / KS;
    const int NITv = pend - pbeg;          // 110 or 111
    const int nodeBase = 2 * pbeg;

    const float* Jb = J + (size_t)b * N_NODES * 3 * D;
    const float* Pb = g_pan + ((size_t)b * N_NODES + nodeBase) * 1024;

    for (int idx = t; idx < STAGES * 2 * SROW; idx += 256) {
        const int s = idx / (2 * SROW);
        const int rem = idx - s * 2 * SROW;
        const int row = (rem < SROW) ? 7 : 19;
        smg[s * STAGE_F + row * SROW + (rem % SROW)] = 0.0f;
    }

    const int      brow0 = (kc < 3) ? 8 + kc : 3;
    const uint32_t bmsk0 = (kc < 3) ? 0u : 0x80000000u;
    const int      brow1 = (kc < 2) ? 4 + kc : ((kc == 2) ? 11 : 7);
    const uint32_t bmsk1 = (kc < 2) ? 0x80000000u : 0u;

    float acc[4][4][4];
#pragma unroll
    for (int i = 0; i < 4; i++)
#pragma unroll
        for (int j = 0; j < 4; j++)
#pragma unroll
            for (int r = 0; r < 4; r++) acc[i][j][r] = 0.0f;

    const int prow = t >> 5;
    const int scol = (t & 31) * 4;
    const int srowP = (prow < 4) ? 3 + prow : 4 + prow;

    auto issue = [&](int it) {
        const int stg = it & (STAGES - 1);
        float* SB = smg + stg * STAGE_F;
        const float* p0 = Pb + (size_t)(2 * it) * 1024;
        cp_async16(SB + srowP * SROW + scol, p0 + t * 4);
        cp_async16(SB + (12 + srowP) * SROW + scol, p0 + 1024 + t * 4);
        if (t < 96) {
            const float* j0 = Jb + (size_t)(3 * (nodeBase + 2 * it)) * D;
            cp_async16(SB + prow * SROW + scol, j0 + t * 4);
            cp_async16(SB + (12 + prow) * SROW + scol, j0 + 384 + t * 4);
        }
    };

    for (int s = 0; s < STAGES - 1; s++) { if (s < NITv) issue(s); cp_commit(); }

    for (int it = 0; it < NITv; ++it) {
        const int stg = it & (STAGES - 1);
        if (it + STAGES - 1 < NITv) issue(it + STAGES - 1);
        cp_commit();
        cp_wait<STAGES - 1>();
        __syncthreads();

        const float* S0 = smg + stg * STAGE_F;
#pragma unroll
        for (int g = 0; g < 2; ++g) {
            const float* S = S0 + g * 12 * SROW;

            uint32_t bb[4][2];
#pragma unroll
            for (int nt = 0; nt < 4; nt++) {
                const int n = wn + nt * 8 + r0;
                bb[nt][0] = __float_as_uint(S[brow0 * SROW + n]) ^ bmsk0;
                bb[nt][1] = __float_as_uint(S[brow1 * SROW + n]) ^ bmsk1;
            }
#pragma unroll
            for (int mt = 0; mt < 4; mt++) {
                const int m = wm + mt * 16 + r0;
                const uint32_t a0 = tf32c(S[kc * SROW + m]);
                const uint32_t a1 = tf32c(S[kc * SROW + m + 8]);
                const uint32_t a2 = __float_as_uint(S[(kc + 4) * SROW + m]);
                const uint32_t a3 = __float_as_uint(S[(kc + 4) * SROW + m + 8]);
#pragma unroll
                for (int nt = 0; nt < 4; nt++)
                    mma_tf32(acc[mt][nt], a0, a1, a2, a3, bb[nt][0], bb[nt][1]);
            }
        }
        __syncthreads();
    }

    float* out = g_Rp + (((size_t)b * KS + ks) << 14);
#pragma unroll
    for (int mt = 0; mt < 4; mt++) {
        const int m = wm + mt * 16 + r0;
#pragma unroll
        for (int nt = 0; nt < 4; nt++) {
            const int n = wn + nt * 8 + 2 * kc;
            *(float2*)&out[m * 128 + n]       = make_float2(acc[mt][nt][0], acc[mt][nt][1]);
            *(float2*)&out[(m + 8) * 128 + n] = make_float2(acc[mt][nt][2], acc[mt][nt][3]);
        }
    }
}

// ---------------- K2c: reduce split-K partials ----------------
__global__ void reduce_kernel() {
    const int idx = blockIdx.x * 256 + threadIdx.x;
    const int b = idx >> 14;
    const float* p = g_Rp + ((size_t)b * KS << 14) + (idx & 16383);
    float s = 0.0f;
#pragma unroll 8
    for (int k = 0; k < KS; k++) s += p[(size_t)k << 14];
    g_Rm[idx] = s;
}

// ---------------- legacy block reductions (eigen tail) ----------------
__device__ __forceinline__ float blockReduceSum(float v, float* red) {
#pragma unroll
    for (int off = 16; off > 0; off >>= 1) v += __shfl_down_sync(0xffffffffu, v, off);
    if ((threadIdx.x & 31) == 0) red[threadIdx.x >> 5] = v;
    __syncthreads();
    if (threadIdx.x == 0) red[0] = red[0] + red[1] + red[2] + red[3];
    __syncthreads();
    const float r = red[0];
    __syncthreads();
    return r;
}
__device__ __forceinline__ float blockReduceMin(float v, float* red) {
#pragma unroll
    for (int off = 16; off > 0; off >>= 1) v = fminf(v, __shfl_down_sync(0xffffffffu, v, off));
    if ((threadIdx.x & 31) == 0) red[threadIdx.x >> 5] = v;
    __syncthreads();
    if (threadIdx.x == 0) red[0] = fminf(fminf(red[0], red[1]), fminf(red[2], red[3]));
    __syncthreads();
    const float r = red[0];
    __syncthreads();
    return r;
}
__device__ __forceinline__ float blockReduceMax(float v, float* red) {
#pragma unroll
    for (int off = 16; off > 0; off >>= 1) v = fmaxf(v, __shfl_down_sync(0xffffffffu, v, off));
    if ((threadIdx.x & 31) == 0) red[threadIdx.x >> 5] = v;
    __syncthreads();
    if (threadIdx.x == 0) red[0] = fmaxf(fmaxf(red[0], red[1]), fmaxf(red[2], red[3]));
    __syncthreads();
    const float r = red[0];
    __syncthreads();
    return r;
}

// ---------------- K3: fused single-pass Householder + twisted Sturm ----------------
#define ASTR 132
#define SMEM_EIG ((128 * ASTR + 6 * 128 + 64) * 4)

__global__ void eigen_kernel() {
    extern __shared__ float smE[];
    float* A  = smE;                  // 128 x ASTR
    float* xA = A + 128 * ASTR;       // x buffer (even k)
    float* xB = xA + 128;             // x buffer (odd k)
    float* qq = xB + 128;             // q vector
    float* pr = qq + 128;             // praw = A*x (own element), reused as e2
    float* dd = pr + 128;
    float* ee = dd + 128;
    float* red = ee + 128;            // 64

    const int b = blockIdx.x;
    const int t = threadIdx.x;
    const int w = t >> 5, lane = t & 31;
    const float* R = g_Rm + (size_t)b * D * D;

#pragma unroll 4
    for (int i = 0; i < 128; i++)
        A[i * ASTR + t] = 0.5f * (R[i * 128 + t] + R[t * 128 + i]);
    __syncthreads();

    // bootstrap: x = col 0, praw = A*x
    {
        const float xi = (t > 0) ? A[t * ASTR] : 0.0f;
        xA[t] = xi;
        __syncthreads();
        const float4* Ar4 = (const float4*)(A + t * ASTR);
        const float4* X4  = (const float4*)xA;
        float pa[4] = {0.f, 0.f, 0.f, 0.f};
#pragma unroll 4
        for (int q = 0; q < 32; q++) {
            const float4 a = Ar4[q], xv = X4[q];
            pa[q & 3] += a.x * xv.x + a.y * xv.y + a.z * xv.z + a.w * xv.w;
        }
        pr[t] = (pa[0] + pa[1]) + (pa[2] + pa[3]);
        __syncthreads();
    }

    for (int k = 0; k < 126; k++) {
        float* xx = (k & 1) ? xB : xA;       // current x (zeros for t<=k)
        float* xn = (k & 1) ? xA : xB;       // next x
        float* sA = red + (k & 1) * 8;
        float* sB = sA + 4;

        const float xi = xx[t];
        float ws = xi * xi;
#pragma unroll
        for (int off = 16; off > 0; off >>= 1) ws += __shfl_down_sync(0xffffffffu, ws, off);
        if (lane == 0) sA[w] = ws;
        __syncthreads();                                  // (1)
        const float sig = (sA[0] + sA[1]) + (sA[2] + sA[3]);
        const float x0 = xx[k + 1];
        const float nrm = sqrtf(sig);
        const float alpha = (x0 >= 0.0f) ? -nrm : nrm;
        const float H = sig - alpha * x0;
        const float invH = (H > 1e-32f) ? 1.0f / H : 0.0f;
        if (t == 0) ee[k + 1] = alpha;
        const float ut = xi - ((t == k + 1) ? alpha : 0.0f);
        // p = (A u)_t / H = (praw - alpha*A[t][k+1]) / H
        const float p = (t > k) ? (pr[t] - alpha * A[t * ASTR + (k + 1)]) * invH : 0.0f;
        float kv = ut * p;
#pragma unroll
        for (int off = 16; off > 0; off >>= 1) kv += __shfl_down_sync(0xffffffffu, kv, off);
        if (lane == 0) sB[w] = kv;
        __syncthreads();                                  // (2)
        const float Ks = (sB[0] + sB[1]) + (sB[2] + sB[3]);
        const float Kc = Ks * 0.5f * invH;
        const float qt = (t > k) ? (p - Kc * ut) : 0.0f;
        qq[t] = qt;
        __syncthreads();                                  // (3)
        // next x: x'_t = A_new[t][k+1] = A[t][k+1] - ut*q[k+1] - qt*u[k+1]
        const float qk1 = qq[k + 1];
        const float uk1 = xx[k + 1] - alpha;
        xn[t] = (t >= k + 2) ? (A[t * ASTR + (k + 1)] - ut * qk1 - qt * uk1) : 0.0f;
        __syncthreads();                                  // (4)
        // fused pass: rank-2 update + praw_next = A_new * x'
        {
            const int j0 = (k + 1) & ~3;
            const int m = (128 - j0) >> 2;
            float pn[4] = {0.f, 0.f, 0.f, 0.f};
            if (t > k) {
                float4* Ar4 = (float4*)(A + t * ASTR + j0);
                const float4* U4 = (const float4*)(xx + j0);
                const float4* Q4 = (const float4*)(qq + j0);
                const float4* N4 = (const float4*)(xn + j0);
#pragma unroll 4
                for (int q = 0; q < m; q++) {
                    float4 a = Ar4[q];
                    const float4 u4 = U4[q], q4 = Q4[q], n4 = N4[q];
                    a.x -= ut * q4.x + qt * u4.x;
                    a.y -= ut * q4.y + qt * u4.y;
                    a.z -= ut * q4.z + qt * u4.z;
                    a.w -= ut * q4.w + qt * u4.w;
                    pn[q & 3] += a.x * n4.x + a.y * n4.y + a.z * n4.z + a.w * n4.w;
                    Ar4[q] = a;
                }
                // U4 held x (not u): fix the j=k+1 term; xn[k+1]=0 so pn unaffected
                A[t * ASTR + (k + 1)] += alpha * qt;
            }
            pr[t] = (pn[0] + pn[1]) + (pn[2] + pn[3]);
        }
        // no trailing barrier: next iteration's barrier (1) orders the pass
    }
    __syncthreads();

    dd[t] = A[t * ASTR + t];
    if (t == 0) { ee[0] = 0.0f; ee[127] = A[127 * ASTR + 126]; }
    __syncthreads();
    float* e2 = pr;                       // reuse
    e2[t] = ee[t] * ee[t];
    const float rad = fabsf(ee[t]) + ((t < 127) ? fabsf(ee[t + 1]) : 0.0f);
    const float gl = blockReduceMin(dd[t] - rad, red + 16);
    const float gu = blockReduceMax(dd[t] + rad, red + 16);
    __syncthreads();

    const float pivmin = fmaxf(1e-12f * fmaxf(fabsf(gl), fabsf(gu)), 1e-36f);
    float lo = gl, hi = gu;
    for (int iter = 0; iter < 30; ++iter) {
        const float mid = 0.5f * (lo + hi);
        int cnt = 0;
        float qf = dd[0] - mid;
        cnt += (qf < 0.0f);
        float qb = dd[127] - mid;
        cnt += (qb < 0.0f);
#pragma unroll 3
        for (int j = 1; j <= 63; j++) {
            if (fabsf(qf) < pivmin) qf = -pivmin;
            qf = dd[j] - mid - __fdividef(e2[j], qf);
            cnt += (qf < 0.0f);
            if (j <= 62) {
                const int i = 127 - j;
                if (fabsf(qb) < pivmin) qb = -pivmin;
                qb = dd[i] - mid - __fdividef(e2[i + 1], qb);
                cnt += (qb < 0.0f);
            }
        }
        if (fabsf(qf) < pivmin) qf = -pivmin;
        if (fabsf(qb) < pivmin) qb = -pivmin;
        const float gam = dd[64] - mid - __fdividef(e2[64], qf) - __fdividef(e2[65], qb);
        cnt += (gam < 0.0f);
        if (cnt > t) hi = mid; else lo = mid;
    }
    const float lam = 0.5f * (lo + hi);
    const float v = (lam > 0.0f) ? sqrtf(lam) : 0.0f;
    const float s = blockReduceSum(v, red + 16);
    if (t == 0) g_partial[b] = s;
}

// ---------------- K4: mean over batch ----------------
__global__ void finalize_kernel(float* out) {
    out[0] = 0.25f * (g_partial[0] + g_partial[1] + g_partial[2] + g_partial[3]);
}

// ---------------- launch ----------------
extern "C" void kernel_launch(void* const* d_in, const int* in_sizes, int n_in,
                              void* d_out, int out_size) {
    const float* x  = (const float*)d_in[0];
    const float* J  = (const float*)d_in[1];
    const int*   ei = (const int*)d_in[2];
    const int E = in_sizes[2] / 2;
    float* out = (float*)d_out;

    cudaFuncSetAttribute(eigen_kernel,
                         cudaFuncAttributeMaxDynamicSharedMemorySize, SMEM_EIG);
    cudaFuncSetAttribute(gemm_kernel,
                         cudaFuncAttributeMaxDynamicSharedMemorySize, GSMEM);

    rowptr_kernel<<<(N_NODES + 1 + 255) / 256, 256>>>(ei, E);

    dim3 ggeo((N_NODES + 127) / 128, BATCH);
    geom_kernel<<<ggeo, 128>>>(x, ei + E);

    dim3 gbuild(N_NODES / 2, BATCH);
    build_kernel<<<gbuild, 256>>>(J, ei + E);

    dim3 ggemm(KS, BATCH);
    gemm_kernel<<<ggemm, 256, GSMEM>>>(J);
    reduce_kernel<<<BATCH * D * D / 256, 256>>>();

    eigen_kernel<<<BATCH, 128, SMEM_EIG>>>();
    finalize_kernel<<<1, 1>>>(out);
}

// round 11
// speedup vs baseline: 1.3936x; 1.0636x over previous
#include <cuda_runtime.h>
#include <math.h>
#include <stdint.h>

#define N_NODES 16384
#define D 128
#define BATCH 4
#define WPRIME (0.05f/1.05f)
#define EMAX 98304

#define KS 74
#define PAIRS (N_NODES / 2)
#define STAGES 4
#define SROW 136
#define STAGE_F (24 * SROW)
#define GSMEM (STAGES * STAGE_F * 4)

// ---------------- device scratch ----------------
__device__ float g_Rm[BATCH * D * D];
__device__ float g_Rp[(size_t)BATCH * KS * D * D];
__device__ int   g_rowptr[N_NODES + 1];
__device__ float g_partial[BATCH];
__device__ float g_pan[(size_t)BATCH * N_NODES * 1024];
__device__ float4 g_edgev[(size_t)BATCH * EMAX];
__device__ float g_geo[(size_t)BATCH * N_NODES * 12];

__device__ __forceinline__ uint32_t tf32c(float f) {
    uint32_t u; asm("cvt.rna.tf32.f32 %0, %1;" : "=r"(u) : "f"(f)); return u;
}
__device__ __forceinline__ float tf32f(float f) {
    return __uint_as_float(tf32c(f));
}

// ---------------- K1: CSR row pointers ----------------
__global__ void rowptr_kernel(const int* __restrict__ e0, int E) {
    int n = blockIdx.x * blockDim.x + threadIdx.x;
    if (n > N_NODES) return;
    int lo = 0, hi = E;
    while (lo < hi) {
        int mid = (lo + hi) >> 1;
        if (e0[mid] < n) lo = mid + 1; else hi = mid;
    }
    g_rowptr[n] = lo;
}

// ---------------- K1b: per-node geometry ----------------
__global__ void geom_kernel(const float* __restrict__ x, const int* __restrict__ e1arr) {
    const int n = blockIdx.x * blockDim.x + threadIdx.x;
    const int b = blockIdx.y;
    if (n >= N_NODES) return;

    const float* xb = x + (size_t)b * N_NODES * 3;
    const float xn0 = xb[3 * n], xn1 = xb[3 * n + 1], xn2 = xb[3 * n + 2];
    float4* ev = g_edgev + (size_t)b * EMAX;

    float deg = 0.f, s0 = 0.f, s1 = 0.f, s2 = 0.f, G = 0.f;
    float c00 = 0.f, c01 = 0.f, c02 = 0.f, c11 = 0.f, c12 = 0.f, c22 = 0.f;

    const int eBeg = g_rowptr[n], eEnd = g_rowptr[n + 1];
    for (int e = eBeg; e < eEnd; ++e) {
        const int m = e1arr[e];
        const float v0 = xn0 - xb[3 * m];
        const float v1 = xn1 - xb[3 * m + 1];
        const float v2 = xn2 - xb[3 * m + 2];
        ev[e] = make_float4(v0, v1, v2, 0.0f);
        deg += 1.0f; s0 += v0; s1 += v1; s2 += v2;
        const float vv = v0 * v0 + v1 * v1 + v2 * v2;
        G += vv;
        c00 += vv - v0 * v0; c01 -= v0 * v1; c02 -= v0 * v2;
        c11 += vv - v1 * v1; c12 -= v1 * v2; c22 += vv - v2 * v2;
    }

    const float l00 = sqrtf(c00);
    const float il00 = 1.0f / l00;
    const float l10 = c01 * il00, l20 = c02 * il00;
    const float l11 = sqrtf(c11 - l10 * l10);
    const float il11 = 1.0f / l11;
    const float l21 = (c12 - l20 * l10) * il11;
    const float l22 = sqrtf(c22 - l20 * l20 - l21 * l21);
    const float il22 = 1.0f / l22;
    const float Ginv = (G < 1e-6f) ? 0.0f : 1.0f / G;

    float* ge = g_geo + ((size_t)b * N_NODES + n) * 12;
    ge[0] = deg; ge[1] = s0; ge[2] = s1; ge[3] = s2;
    ge[4] = il00; ge[5] = l10; ge[6] = il11;
    ge[7] = l20; ge[8] = l21; ge[9] = il22;
    ge[10] = WPRIME * Ginv; ge[11] = 0.0f;
}

// ---------------- K2a: build panels (deg-6 fast path, pre-rounded TF32) ----------------
__global__ void __launch_bounds__(256)
build_kernel(const float* __restrict__ J, const int* __restrict__ e1arr) {
    const int b = blockIdx.y;
    const int n = blockIdx.x * 2 + (threadIdx.x >> 7);
    const int c = threadIdx.x & 127;

    const float* Jb = J + (size_t)b * N_NODES * 3 * D;
    const float4* ev = g_edgev + (size_t)b * EMAX;

    const float* Jn = Jb + (size_t)(3 * n) * D + c;
    const float Jn0 = Jn[0], Jn1 = Jn[D], Jn2 = Jn[2 * D];

    float nb0 = 0.f, nb1 = 0.f, nb2 = 0.f;
    float T0 = 0.f, T1 = 0.f, T2 = 0.f, u = 0.f;

    const int eBeg = g_rowptr[n], eEnd = g_rowptr[n + 1];
    const int degn = eEnd - eBeg;

    if (degn == 6) {
        // straight-line: batch all loads (high MLP), then accumulate
        int mm[6];
#pragma unroll
        for (int i = 0; i < 6; i++) mm[i] = e1arr[eBeg + i];
        float4 vv[6];
#pragma unroll
        for (int i = 0; i < 6; i++) vv[i] = ev[eBeg + i];
        float jm0[6], jm1[6], jm2[6];
#pragma unroll
        for (int i = 0; i < 6; i++) {
            const float* Jm = Jb + (size_t)(3 * mm[i]) * D + c;
            jm0[i] = Jm[0]; jm1[i] = Jm[D]; jm2[i] = Jm[2 * D];
        }
#pragma unroll
        for (int i = 0; i < 6; i++) {
            const float4 v = vv[i];
            nb0 += jm0[i]; nb1 += jm1[i]; nb2 += jm2[i];
            T0 += v.y * jm2[i] - v.z * jm1[i];
            T1 += v.z * jm0[i] - v.x * jm2[i];
            T2 += v.x * jm1[i] - v.y * jm0[i];
            u  += v.x * jm0[i] + v.y * jm1[i] + v.z * jm2[i];
        }
    } else {
#pragma unroll 2
        for (int e = eBeg; e < eEnd; ++e) {
            const int m = e1arr[e];
            const float4 v = ev[e];
            const float* Jm = Jb + (size_t)(3 * m) * D + c;
            const float Jm0 = Jm[0], Jm1 = Jm[D], Jm2 = Jm[2 * D];
            nb0 += Jm0; nb1 += Jm1; nb2 += Jm2;
            T0 += v.y * Jm2 - v.z * Jm1;
            T1 += v.z * Jm0 - v.x * Jm2;
            T2 += v.x * Jm1 - v.y * Jm0;
            u  += v.x * Jm0 + v.y * Jm1 + v.z * Jm2;
        }
    }

    const float* ge = g_geo + ((size_t)b * N_NODES + n) * 12;
    const float deg = ge[0], s0 = ge[1], s1 = ge[2], s2 = ge[3];
    const float il00 = ge[4], l10 = ge[5], il11 = ge[6];
    const float l20 = ge[7], l21 = ge[8], il22 = ge[9];
    const float wGinv = ge[10];

    const float LJ0 = 2.0f * (deg * Jn0 - nb0);
    const float LJ1 = 2.0f * (deg * Jn1 - nb1);
    const float LJ2 = 2.0f * (deg * Jn2 - nb2);
    const float B0 = T0 + s2 * Jn1 - s1 * Jn2;
    const float B1 = T1 - s2 * Jn0 + s0 * Jn2;
    const float B2 = T2 + s1 * Jn0 - s0 * Jn1;
    const float y = u - (s0 * Jn0 + s1 * Jn1 + s2 * Jn2);
    const float Z0 = B0 * il00;
    const float Z1 = (B1 - l10 * Z0) * il11;
    const float Z2 = (B2 - l20 * Z0 - l21 * Z1) * il22;

    float* P = g_pan + ((size_t)b * N_NODES + n) * 1024 + c;
    P[0*128] = tf32f(Z0);   P[1*128] = tf32f(Z1);   P[2*128] = tf32f(Z2);
    P[3*128] = tf32f(y);
    P[4*128] = tf32f(LJ0);  P[5*128] = tf32f(LJ1);  P[6*128] = tf32f(LJ2);
    P[7*128] = tf32f(-wGinv * y);
}

// ---------------- K2b: TF32 split-K GEMM (unchanged, known good) ----------------
__device__ __forceinline__ void cp_async16(void* dst_smem, const void* src) {
    uint32_t d = (uint32_t)__cvta_generic_to_shared(dst_smem);
    asm volatile("cp.async.cg.shared.global [%0], [%1], 16;" :: "r"(d), "l"(src));
}
__device__ __forceinline__ void cp_commit() { asm volatile("cp.async.commit_group;"); }
template<int NN> __device__ __forceinline__ void cp_wait() {
    asm volatile("cp.async.wait_group %0;" :: "n"(NN));
}
__device__ __forceinline__ void mma_tf32(float* d, uint32_t a0, uint32_t a1,
                                         uint32_t a2, uint32_t a3,
                                         uint32_t b0, uint32_t b1) {
    asm volatile(
        "mma.sync.aligned.m16n8k8.row.col.f32.tf32.tf32.f32 "
        "{%0,%1,%2,%3}, {%4,%5,%6,%7}, {%8,%9}, {%0,%1,%2,%3};"
        : "+f"(d[0]), "+f"(d[1]), "+f"(d[2]), "+f"(d[3])
        : "r"(a0), "r"(a1), "r"(a2), "r"(a3), "r"(b0), "r"(b1));
}

__global__ void __launch_bounds__(256, 2)
gemm_kernel(const float* __restrict__ J) {
    extern __shared__ float smg[];

    const int b = blockIdx.y, ks = blockIdx.x;
    const int t = threadIdx.x;
    const int wid = t >> 5, lane = t & 31;
    const int wm = (wid >> 2) * 64;
    const int wn = (wid & 3) * 32;
    const int r0 = lane >> 2, kc = lane & 3;

    const int pbeg = (ks * PAIRS) / KS;
    const int pend = ((ks + 1) * PAIRS) / KS;
    const int NITv = pend - pbeg;
    const int nodeBase = 2 * pbeg;

    const float* Jb = J + (size_t)b * N_NODES * 3 * D;
    const float* Pb = g_pan + ((size_t)b * N_NODES + nodeBase) * 1024;

    for (int idx = t; idx < STAGES * 2 * SROW; idx += 256) {
        const int s = idx / (2 * SROW);
        const int rem = idx - s * 2 * SROW;
        const int row = (rem < SROW) ? 7 : 19;
        smg[s * STAGE_F + row * SROW + (rem % SROW)] = 0.0f;
    }

    const int      brow0 = (kc < 3) ? 8 + kc : 3;
    const uint32_t bmsk0 = (kc < 3) ? 0u : 0x80000000u;
    const int      brow1 = (kc < 2) ? 4 + kc : ((kc == 2) ? 11 : 7);
    const uint32_t bmsk1 = (kc < 2) ? 0x80000000u : 0u;

    float acc[4][4][4];
#pragma unroll
    for (int i = 0; i < 4; i++)
#pragma unroll
        for (int j = 0; j < 4; j++)
#pragma unroll
            for (int r = 0; r < 4; r++) acc[i][j][r] = 0.0f;

    const int prow = t >> 5;
    const int scol = (t & 31) * 4;
    const int srowP = (prow < 4) ? 3 + prow : 4 + prow;

    auto issue = [&](int it) {
        const int stg = it & (STAGES - 1);
        float* SB = smg + stg * STAGE_F;
        const float* p0 = Pb + (size_t)(2 * it) * 1024;
        cp_async16(SB + srowP * SROW + scol, p0 + t * 4);
        cp_async16(SB + (12 + srowP) * SROW + scol, p0 + 1024 + t * 4);
        if (t < 96) {
            const float* j0 = Jb + (size_t)(3 * (nodeBase + 2 * it)) * D;
            cp_async16(SB + prow * SROW + scol, j0 + t * 4);
            cp_async16(SB + (12 + prow) * SROW + scol, j0 + 384 + t * 4);
        }
    };

    for (int s = 0; s < STAGES - 1; s++) { if (s < NITv) issue(s); cp_commit(); }

    for (int it = 0; it < NITv; ++it) {
        const int stg = it & (STAGES - 1);
        if (it + STAGES - 1 < NITv) issue(it + STAGES - 1);
        cp_commit();
        cp_wait<STAGES - 1>();
        __syncthreads();

        const float* S0 = smg + stg * STAGE_F;
#pragma unroll
        for (int g = 0; g < 2; ++g) {
            const float* S = S0 + g * 12 * SROW;

            uint32_t bb[4][2];
#pragma unroll
            for (int nt = 0; nt < 4; nt++) {
                const int n = wn + nt * 8 + r0;
                bb[nt][0] = __float_as_uint(S[brow0 * SROW + n]) ^ bmsk0;
                bb[nt][1] = __float_as_uint(S[brow1 * SROW + n]) ^ bmsk1;
            }
#pragma unroll
            for (int mt = 0; mt < 4; mt++) {
                const int m = wm + mt * 16 + r0;
                const uint32_t a0 = tf32c(S[kc * SROW + m]);
                const uint32_t a1 = tf32c(S[kc * SROW + m + 8]);
                const uint32_t a2 = __float_as_uint(S[(kc + 4) * SROW + m]);
                const uint32_t a3 = __float_as_uint(S[(kc + 4) * SROW + m + 8]);
#pragma unroll
                for (int nt = 0; nt < 4; nt++)
                    mma_tf32(acc[mt][nt], a0, a1, a2, a3, bb[nt][0], bb[nt][1]);
            }
        }
        __syncthreads();
    }

    float* out = g_Rp + (((size_t)b * KS + ks) << 14);
#pragma unroll
    for (int mt = 0; mt < 4; mt++) {
        const int m = wm + mt * 16 + r0;
#pragma unroll
        for (int nt = 0; nt < 4; nt++) {
            const int n = wn + nt * 8 + 2 * kc;
            *(float2*)&out[m * 128 + n]       = make_float2(acc[mt][nt][0], acc[mt][nt][1]);
            *(float2*)&out[(m + 8) * 128 + n] = make_float2(acc[mt][nt][2], acc[mt][nt][3]);
        }
    }
}

// ---------------- K2c: reduce split-K partials ----------------
__global__ void reduce_kernel() {
    const int idx = blockIdx.x * 256 + threadIdx.x;
    const int b = idx >> 14;
    const float* p = g_Rp + ((size_t)b * KS << 14) + (idx & 16383);
    float s = 0.0f;
#pragma unroll 8
    for (int k = 0; k < KS; k++) s += p[(size_t)k << 14];
    g_Rm[idx] = s;
}

// ---------------- legacy block reductions (eigen tail) ----------------
__device__ __forceinline__ float blockReduceSum(float v, float* red) {
#pragma unroll
    for (int off = 16; off > 0; off >>= 1) v += __shfl_down_sync(0xffffffffu, v, off);
    if ((threadIdx.x & 31) == 0) red[threadIdx.x >> 5] = v;
    __syncthreads();
    if (threadIdx.x == 0) red[0] = red[0] + red[1] + red[2] + red[3];
    __syncthreads();
    const float r = red[0];
    __syncthreads();
    return r;
}
__device__ __forceinline__ float blockReduceMin(float v, float* red) {
#pragma unroll
    for (int off = 16; off > 0; off >>= 1) v = fminf(v, __shfl_down_sync(0xffffffffu, v, off));
    if ((threadIdx.x & 31) == 0) red[threadIdx.x >> 5] = v;
    __syncthreads();
    if (threadIdx.x == 0) red[0] = fminf(fminf(red[0], red[1]), fminf(red[2], red[3]));
    __syncthreads();
    const float r = red[0];
    __syncthreads();
    return r;
}
__device__ __forceinline__ float blockReduceMax(float v, float* red) {
#pragma unroll
    for (int off = 16; off > 0; off >>= 1) v = fmaxf(v, __shfl_down_sync(0xffffffffu, v, off));
    if ((threadIdx.x & 31) == 0) red[threadIdx.x >> 5] = v;
    __syncthreads();
    if (threadIdx.x == 0) red[0] = fmaxf(fmaxf(red[0], red[1]), fmaxf(red[2], red[3]));
    __syncthreads();
    const float r = red[0];
    __syncthreads();
    return r;
}

// ---------------- K3: fused Householder (3 barriers/iter) + twisted Sturm ----------------
#define ASTR 132
#define SMEM_EIG ((128 * ASTR + 6 * 128 + 64) * 4)

__global__ void eigen_kernel() {
    extern __shared__ float smE[];
    float* A  = smE;                  // 128 x ASTR
    float* xA = A + 128 * ASTR;
    float* xB = xA + 128;
    float* qq = xB + 128;
    float* pr = qq + 128;
    float* dd = pr + 128;
    float* ee = dd + 128;
    float* red = ee + 128;            // 64

    const int b = blockIdx.x;
    const int t = threadIdx.x;
    const int w = t >> 5, lane = t & 31;
    const float* R = g_Rm + (size_t)b * D * D;

#pragma unroll 4
    for (int i = 0; i < 128; i++)
        A[i * ASTR + t] = 0.5f * (R[i * 128 + t] + R[t * 128 + i]);
    __syncthreads();

    // bootstrap: x = col 0, praw = A*x
    {
        const float xi = (t > 0) ? A[t * ASTR] : 0.0f;
        xA[t] = xi;
        __syncthreads();
        const float4* Ar4 = (const float4*)(A + t * ASTR);
        const float4* X4  = (const float4*)xA;
        float pa[4] = {0.f, 0.f, 0.f, 0.f};
#pragma unroll 4
        for (int q = 0; q < 32; q++) {
            const float4 a = Ar4[q], xv = X4[q];
            pa[q & 3] += a.x * xv.x + a.y * xv.y + a.z * xv.z + a.w * xv.w;
        }
        pr[t] = (pa[0] + pa[1]) + (pa[2] + pa[3]);
        __syncthreads();
    }

    for (int k = 0; k < 126; k++) {
        float* xx = (k & 1) ? xB : xA;
        float* xn = (k & 1) ? xA : xB;
        float* sA = red + (k & 1) * 8;
        float* sB = sA + 4;

        const float xi = xx[t];
        float ws = xi * xi;
#pragma unroll
        for (int off = 16; off > 0; off >>= 1) ws += __shfl_down_sync(0xffffffffu, ws, off);
        if (lane == 0) sA[w] = ws;
        __syncthreads();                                  // (1)
        const float sig = (sA[0] + sA[1]) + (sA[2] + sA[3]);
        const float x0 = xx[k + 1];
        const float nrm = sqrtf(sig);
        const float alpha = (x0 >= 0.0f) ? -nrm : nrm;
        const float H = sig - alpha * x0;
        const float invH = (H > 1e-32f) ? 1.0f / H : 0.0f;
        if (t == 0) ee[k + 1] = alpha;
        const float ut = xi - ((t == k + 1) ? alpha : 0.0f);
        const float p = (t > k) ? (pr[t] - alpha * A[t * ASTR + (k + 1)]) * invH : 0.0f;
        float kv = ut * p;
#pragma unroll
        for (int off = 16; off > 0; off >>= 1) kv += __shfl_down_sync(0xffffffffu, kv, off);
        if (lane == 0) sB[w] = kv;
        __syncthreads();                                  // (2)
        const float Ks = (sB[0] + sB[1]) + (sB[2] + sB[3]);
        const float Kc = Ks * 0.5f * invH;
        const float qt = (t > k) ? (p - Kc * ut) : 0.0f;
        // redundant q[k+1]: all inputs are barrier-(1)-ordered broadcasts
        const float uk1 = x0 - alpha;
        const float pk1 = (pr[k + 1] - alpha * A[(k + 1) * ASTR + (k + 1)]) * invH;
        const float qk1 = pk1 - Kc * uk1;
        qq[t] = qt;
        xn[t] = (t >= k + 2) ? (A[t * ASTR + (k + 1)] - ut * qk1 - qt * uk1) : 0.0f;
        __syncthreads();                                  // (3)
        // fused pass: rank-2 update + praw_next = A_new * x'
        {
            const int j0 = (k + 1) & ~3;
            const int m = (128 - j0) >> 2;
            float pn[4] = {0.f, 0.f, 0.f, 0.f};
            if (t > k) {
                float4* Ar4 = (float4*)(A + t * ASTR + j0);
                const float4* U4 = (const float4*)(xx + j0);
                const float4* Q4 = (const float4*)(qq + j0);
                const float4* N4 = (const float4*)(xn + j0);
#pragma unroll 4
                for (int q = 0; q < m; q++) {
                    float4 a = Ar4[q];
                    const float4 u4 = U4[q], q4 = Q4[q], n4 = N4[q];
                    a.x -= ut * q4.x + qt * u4.x;
                    a.y -= ut * q4.y + qt * u4.y;
                    a.z -= ut * q4.z + qt * u4.z;
                    a.w -= ut * q4.w + qt * u4.w;
                    pn[q & 3] += a.x * n4.x + a.y * n4.y + a.z * n4.z + a.w * n4.w;
                    Ar4[q] = a;
                }
                // xx held x (not u): fix j=k+1 term; xn[k+1]=0 so pn unaffected
                A[t * ASTR + (k + 1)] += alpha * qt;
            }
            pr[t] = (pn[0] + pn[1]) + (pn[2] + pn[3]);
        }
        // next iteration's barrier (1) orders the pass
    }
    __syncthreads();

    dd[t] = A[t * ASTR + t];
    if (t == 0) { ee[0] = 0.0f; ee[127] = A[127 * ASTR + 126]; }
    __syncthreads();
    float* e2 = pr;
    e2[t] = ee[t] * ee[t];
    const float rad = fabsf(ee[t]) + ((t < 127) ? fabsf(ee[t + 1]) : 0.0f);
    const float gl = blockReduceMin(dd[t] - rad, red + 16);
    const float gu = blockReduceMax(dd[t] + rad, red + 16);
    __syncthreads();

    const float pivmin = fmaxf(1e-12f * fmaxf(fabsf(gl), fabsf(gu)), 1e-36f);
    float lo = gl, hi = gu;
    for (int iter = 0; iter < 26; ++iter) {
        const float mid = 0.5f * (lo + hi);
        int cnt = 0;
        float qf = dd[0] - mid;
        cnt += (qf < 0.0f);
        float qb = dd[127] - mid;
        cnt += (qb < 0.0f);
#pragma unroll 3
        for (int j = 1; j <= 63; j++) {
            if (fabsf(qf) < pivmin) qf = -pivmin;
            qf = dd[j] - mid - __fdividef(e2[j], qf);
            cnt += (qf < 0.0f);
            if (j <= 62) {
                const int i = 127 - j;
                if (fabsf(qb) < pivmin) qb = -pivmin;
                qb = dd[i] - mid - __fdividef(e2[i + 1], qb);
                cnt += (qb < 0.0f);
            }
        }
        if (fabsf(qf) < pivmin) qf = -pivmin;
        if (fabsf(qb) < pivmin) qb = -pivmin;
        const float gam = dd[64] - mid - __fdividef(e2[64], qf) - __fdividef(e2[65], qb);
        cnt += (gam < 0.0f);
        if (cnt > t) hi = mid; else lo = mid;
    }
    const float lam = 0.5f * (lo + hi);
    const float v = (lam > 0.0f) ? sqrtf(lam) : 0.0f;
    const float s = blockReduceSum(v, red + 16);
    if (t == 0) g_partial[b] = s;
}

// ---------------- K4: mean over batch ----------------
__global__ void finalize_kernel(float* out) {
    out[0] = 0.25f * (g_partial[0] + g_partial[1] + g_partial[2] + g_partial[3]);
}

// ---------------- launch ----------------
extern "C" void kernel_launch(void* const* d_in, const int* in_sizes, int n_in,
                              void* d_out, int out_size) {
    const float* x  = (const float*)d_in[0];
    const float* J  = (const float*)d_in[1];
    const int*   ei = (const int*)d_in[2];
    const int E = in_sizes[2] / 2;
    float* out = (float*)d_out;

    cudaFuncSetAttribute(eigen_kernel,
                         cudaFuncAttributeMaxDynamicSharedMemorySize, SMEM_EIG);
    cudaFuncSetAttribute(gemm_kernel,
                         cudaFuncAttributeMaxDynamicSharedMemorySize, GSMEM);

    rowptr_kernel<<<(N_NODES + 1 + 255) / 256, 256>>>(ei, E);

    dim3 ggeo((N_NODES + 127) / 128, BATCH);
    geom_kernel<<<ggeo, 128>>>(x, ei + E);

    dim3 gbuild(N_NODES / 2, BATCH);
    build_kernel<<<gbuild, 256>>>(J, ei + E);

    dim3 ggemm(KS, BATCH);
    gemm_kernel<<<ggemm, 256, GSMEM>>>(J);
    reduce_kernel<<<BATCH * D * D / 256, 256>>>();

    eigen_kernel<<<BATCH, 128, SMEM_EIG>>>();
    finalize_kernel<<<1, 1>>>(out);
}

// round 12
// speedup vs baseline: 1.4232x; 1.0212x over previous
#include <cuda_runtime.h>
#include <math.h>
#include <float.h>
#include <stdint.h>

#define N_NODES 16384
#define D 128
#define BATCH 4
#define WPRIME (0.05f/1.05f)
#define EMAX 98304

#define KS 74
#define PAIRS (N_NODES / 2)
#define STAGES 4
#define SROW 136
#define STAGE_F (24 * SROW)
#define GSMEM (STAGES * STAGE_F * 4)

// ---------------- device scratch ----------------
__device__ float g_Rm[BATCH * D * D];
__device__ float g_Rp[(size_t)BATCH * KS * D * D];
__device__ int   g_rowptr[N_NODES + 1];
__device__ float g_partial[BATCH];
__device__ float g_pan[(size_t)BATCH * N_NODES * 1024];
__device__ float4 g_edgev[(size_t)BATCH * EMAX];
__device__ float g_geo[(size_t)BATCH * N_NODES * 12];

__device__ __forceinline__ uint32_t tf32c(float f) {
    uint32_t u; asm("cvt.rna.tf32.f32 %0, %1;" : "=r"(u) : "f"(f)); return u;
}
__device__ __forceinline__ float tf32f(float f) {
    return __uint_as_float(tf32c(f));
}

// ---------------- K1: CSR row pointers ----------------
__global__ void rowptr_kernel(const int* __restrict__ e0, int E) {
    int n = blockIdx.x * blockDim.x + threadIdx.x;
    if (n > N_NODES) return;
    int lo = 0, hi = E;
    while (lo < hi) {
        int mid = (lo + hi) >> 1;
        if (e0[mid] < n) lo = mid + 1; else hi = mid;
    }
    g_rowptr[n] = lo;
}

// ---------------- K1b: per-node geometry ----------------
__global__ void geom_kernel(const float* __restrict__ x, const int* __restrict__ e1arr) {
    const int n = blockIdx.x * blockDim.x + threadIdx.x;
    const int b = blockIdx.y;
    if (n >= N_NODES) return;

    const float* xb = x + (size_t)b * N_NODES * 3;
    const float xn0 = xb[3 * n], xn1 = xb[3 * n + 1], xn2 = xb[3 * n + 2];
    float4* ev = g_edgev + (size_t)b * EMAX;

    float deg = 0.f, s0 = 0.f, s1 = 0.f, s2 = 0.f, G = 0.f;
    float c00 = 0.f, c01 = 0.f, c02 = 0.f, c11 = 0.f, c12 = 0.f, c22 = 0.f;

    const int eBeg = g_rowptr[n], eEnd = g_rowptr[n + 1];
    for (int e = eBeg; e < eEnd; ++e) {
        const int m = e1arr[e];
        const float v0 = xn0 - xb[3 * m];
        const float v1 = xn1 - xb[3 * m + 1];
        const float v2 = xn2 - xb[3 * m + 2];
        ev[e] = make_float4(v0, v1, v2, 0.0f);
        deg += 1.0f; s0 += v0; s1 += v1; s2 += v2;
        const float vv = v0 * v0 + v1 * v1 + v2 * v2;
        G += vv;
        c00 += vv - v0 * v0; c01 -= v0 * v1; c02 -= v0 * v2;
        c11 += vv - v1 * v1; c12 -= v1 * v2; c22 += vv - v2 * v2;
    }

    const float l00 = sqrtf(c00);
    const float il00 = 1.0f / l00;
    const float l10 = c01 * il00, l20 = c02 * il00;
    const float l11 = sqrtf(c11 - l10 * l10);
    const float il11 = 1.0f / l11;
    const float l21 = (c12 - l20 * l10) * il11;
    const float l22 = sqrtf(c22 - l20 * l20 - l21 * l21);
    const float il22 = 1.0f / l22;
    const float Ginv = (G < 1e-6f) ? 0.0f : 1.0f / G;

    float* ge = g_geo + ((size_t)b * N_NODES + n) * 12;
    ge[0] = deg; ge[1] = s0; ge[2] = s1; ge[3] = s2;
    ge[4] = il00; ge[5] = l10; ge[6] = il11;
    ge[7] = l20; ge[8] = l21; ge[9] = il22;
    ge[10] = WPRIME * Ginv; ge[11] = 0.0f;
}

// ---------------- K2a: build panels (deg-6 fast path, pre-rounded TF32) ----------------
__global__ void __launch_bounds__(256)
build_kernel(const float* __restrict__ J, const int* __restrict__ e1arr) {
    const int b = blockIdx.y;
    const int n = blockIdx.x * 2 + (threadIdx.x >> 7);
    const int c = threadIdx.x & 127;

    const float* Jb = J + (size_t)b * N_NODES * 3 * D;
    const float4* ev = g_edgev + (size_t)b * EMAX;

    const float* Jn = Jb + (size_t)(3 * n) * D + c;
    const float Jn0 = Jn[0], Jn1 = Jn[D], Jn2 = Jn[2 * D];

    float nb0 = 0.f, nb1 = 0.f, nb2 = 0.f;
    float T0 = 0.f, T1 = 0.f, T2 = 0.f, u = 0.f;

    const int eBeg = g_rowptr[n], eEnd = g_rowptr[n + 1];
    const int degn = eEnd - eBeg;

    if (degn == 6) {
        int mm[6];
#pragma unroll
        for (int i = 0; i < 6; i++) mm[i] = e1arr[eBeg + i];
        float4 vv[6];
#pragma unroll
        for (int i = 0; i < 6; i++) vv[i] = ev[eBeg + i];
        float jm0[6], jm1[6], jm2[6];
#pragma unroll
        for (int i = 0; i < 6; i++) {
            const float* Jm = Jb + (size_t)(3 * mm[i]) * D + c;
            jm0[i] = Jm[0]; jm1[i] = Jm[D]; jm2[i] = Jm[2 * D];
        }
#pragma unroll
        for (int i = 0; i < 6; i++) {
            const float4 v = vv[i];
            nb0 += jm0[i]; nb1 += jm1[i]; nb2 += jm2[i];
            T0 += v.y * jm2[i] - v.z * jm1[i];
            T1 += v.z * jm0[i] - v.x * jm2[i];
            T2 += v.x * jm1[i] - v.y * jm0[i];
            u  += v.x * jm0[i] + v.y * jm1[i] + v.z * jm2[i];
        }
    } else {
#pragma unroll 2
        for (int e = eBeg; e < eEnd; ++e) {
            const int m = e1arr[e];
            const float4 v = ev[e];
            const float* Jm = Jb + (size_t)(3 * m) * D + c;
            const float Jm0 = Jm[0], Jm1 = Jm[D], Jm2 = Jm[2 * D];
            nb0 += Jm0; nb1 += Jm1; nb2 += Jm2;
            T0 += v.y * Jm2 - v.z * Jm1;
            T1 += v.z * Jm0 - v.x * Jm2;
            T2 += v.x * Jm1 - v.y * Jm0;
            u  += v.x * Jm0 + v.y * Jm1 + v.z * Jm2;
        }
    }

    const float* ge = g_geo + ((size_t)b * N_NODES + n) * 12;
    const float deg = ge[0], s0 = ge[1], s1 = ge[2], s2 = ge[3];
    const float il00 = ge[4], l10 = ge[5], il11 = ge[6];
    const float l20 = ge[7], l21 = ge[8], il22 = ge[9];
    const float wGinv = ge[10];

    const float LJ0 = 2.0f * (deg * Jn0 - nb0);
    const float LJ1 = 2.0f * (deg * Jn1 - nb1);
    const float LJ2 = 2.0f * (deg * Jn2 - nb2);
    const float B0 = T0 + s2 * Jn1 - s1 * Jn2;
    const float B1 = T1 - s2 * Jn0 + s0 * Jn2;
    const float B2 = T2 + s1 * Jn0 - s0 * Jn1;
    const float y = u - (s0 * Jn0 + s1 * Jn1 + s2 * Jn2);
    const float Z0 = B0 * il00;
    const float Z1 = (B1 - l10 * Z0) * il11;
    const float Z2 = (B2 - l20 * Z0 - l21 * Z1) * il22;

    float* P = g_pan + ((size_t)b * N_NODES + n) * 1024 + c;
    P[0*128] = tf32f(Z0);   P[1*128] = tf32f(Z1);   P[2*128] = tf32f(Z2);
    P[3*128] = tf32f(y);
    P[4*128] = tf32f(LJ0);  P[5*128] = tf32f(LJ1);  P[6*128] = tf32f(LJ2);
    P[7*128] = tf32f(-wGinv * y);
}

// ---------------- K2b: TF32 split-K GEMM (unchanged, known good) ----------------
__device__ __forceinline__ void cp_async16(void* dst_smem, const void* src) {
    uint32_t d = (uint32_t)__cvta_generic_to_shared(dst_smem);
    asm volatile("cp.async.cg.shared.global [%0], [%1], 16;" :: "r"(d), "l"(src));
}
__device__ __forceinline__ void cp_commit() { asm volatile("cp.async.commit_group;"); }
template<int NN> __device__ __forceinline__ void cp_wait() {
    asm volatile("cp.async.wait_group %0;" :: "n"(NN));
}
__device__ __forceinline__ void mma_tf32(float* d, uint32_t a0, uint32_t a1,
                                         uint32_t a2, uint32_t a3,
                                         uint32_t b0, uint32_t b1) {
    asm volatile(
        "mma.sync.aligned.m16n8k8.row.col.f32.tf32.tf32.f32 "
        "{%0,%1,%2,%3}, {%4,%5,%6,%7}, {%8,%9}, {%0,%1,%2,%3};"
        : "+f"(d[0]), "+f"(d[1]), "+f"(d[2]), "+f"(d[3])
        : "r"(a0), "r"(a1), "r"(a2), "r"(a3), "r"(b0), "r"(b1));
}

__global__ void __launch_bounds__(256, 2)
gemm_kernel(const float* __restrict__ J) {
    extern __shared__ float smg[];

    const int b = blockIdx.y, ks = blockIdx.x;
    const int t = threadIdx.x;
    const int wid = t >> 5, lane = t & 31;
    const int wm = (wid >> 2) * 64;
    const int wn = (wid & 3) * 32;
    const int r0 = lane >> 2, kc = lane & 3;

    const int pbeg = (ks * PAIRS) / KS;
    const int pend = ((ks + 1) * PAIRS) / KS;
    const int NITv = pend - pbeg;
    const int nodeBase = 2 * pbeg;

    const float* Jb = J + (size_t)b * N_NODES * 3 * D;
    const float* Pb = g_pan + ((size_t)b * N_NODES + nodeBase) * 1024;

    for (int idx = t; idx < STAGES * 2 * SROW; idx += 256) {
        const int s = idx / (2 * SROW);
        const int rem = idx - s * 2 * SROW;
        const int row = (rem < SROW) ? 7 : 19;
        smg[s * STAGE_F + row * SROW + (rem % SROW)] = 0.0f;
    }

    const int      brow0 = (kc < 3) ? 8 + kc : 3;
    const uint32_t bmsk0 = (kc < 3) ? 0u : 0x80000000u;
    const int      brow1 = (kc < 2) ? 4 + kc : ((kc == 2) ? 11 : 7);
    const uint32_t bmsk1 = (kc < 2) ? 0x80000000u : 0u;

    float acc[4][4][4];
#pragma unroll
    for (int i = 0; i < 4; i++)
#pragma unroll
        for (int j = 0; j < 4; j++)
#pragma unroll
            for (int r = 0; r < 4; r++) acc[i][j][r] = 0.0f;

    const int prow = t >> 5;
    const int scol = (t & 31) * 4;
    const int srowP = (prow < 4) ? 3 + prow : 4 + prow;

    auto issue = [&](int it) {
        const int stg = it & (STAGES - 1);
        float* SB = smg + stg * STAGE_F;
        const float* p0 = Pb + (size_t)(2 * it) * 1024;
        cp_async16(SB + srowP * SROW + scol, p0 + t * 4);
        cp_async16(SB + (12 + srowP) * SROW + scol, p0 + 1024 + t * 4);
        if (t < 96) {
            const float* j0 = Jb + (size_t)(3 * (nodeBase + 2 * it)) * D;
            cp_async16(SB + prow * SROW + scol, j0 + t * 4);
            cp_async16(SB + (12 + prow) * SROW + scol, j0 + 384 + t * 4);
        }
    };

    for (int s = 0; s < STAGES - 1; s++) { if (s < NITv) issue(s); cp_commit(); }

    for (int it = 0; it < NITv; ++it) {
        const int stg = it & (STAGES - 1);
        if (it + STAGES - 1 < NITv) issue(it + STAGES - 1);
        cp_commit();
        cp_wait<STAGES - 1>();
        __syncthreads();

        const float* S0 = smg + stg * STAGE_F;
#pragma unroll
        for (int g = 0; g < 2; ++g) {
            const float* S = S0 + g * 12 * SROW;

            uint32_t bb[4][2];
#pragma unroll
            for (int nt = 0; nt < 4; nt++) {
                const int n = wn + nt * 8 + r0;
                bb[nt][0] = __float_as_uint(S[brow0 * SROW + n]) ^ bmsk0;
                bb[nt][1] = __float_as_uint(S[brow1 * SROW + n]) ^ bmsk1;
            }
#pragma unroll
            for (int mt = 0; mt < 4; mt++) {
                const int m = wm + mt * 16 + r0;
                const uint32_t a0 = tf32c(S[kc * SROW + m]);
                const uint32_t a1 = tf32c(S[kc * SROW + m + 8]);
                const uint32_t a2 = __float_as_uint(S[(kc + 4) * SROW + m]);
                const uint32_t a3 = __float_as_uint(S[(kc + 4) * SROW + m + 8]);
#pragma unroll
                for (int nt = 0; nt < 4; nt++)
                    mma_tf32(acc[mt][nt], a0, a1, a2, a3, bb[nt][0], bb[nt][1]);
            }
        }
        __syncthreads();
    }

    float* out = g_Rp + (((size_t)b * KS + ks) << 14);
#pragma unroll
    for (int mt = 0; mt < 4; mt++) {
        const int m = wm + mt * 16 + r0;
#pragma unroll
        for (int nt = 0; nt < 4; nt++) {
            const int n = wn + nt * 8 + 2 * kc;
            *(float2*)&out[m * 128 + n]       = make_float2(acc[mt][nt][0], acc[mt][nt][1]);
            *(float2*)&out[(m + 8) * 128 + n] = make_float2(acc[mt][nt][2], acc[mt][nt][3]);
        }
    }
}

// ---------------- K2c: reduce split-K partials ----------------
__global__ void reduce_kernel() {
    const int idx = blockIdx.x * 256 + threadIdx.x;
    const int b = idx >> 14;
    const float* p = g_Rp + ((size_t)b * KS << 14) + (idx & 16383);
    float s = 0.0f;
#pragma unroll 8
    for (int k = 0; k < KS; k++) s += p[(size_t)k << 14];
    g_Rm[idx] = s;
}

// ---------------- 256-thread (8-warp) 1-sync-style reductions for eigen tail ----------------
__device__ __forceinline__ float brs256(float v, float* red) {
#pragma unroll
    for (int off = 16; off > 0; off >>= 1) v += __shfl_down_sync(0xffffffffu, v, off);
    if ((threadIdx.x & 31) == 0) red[threadIdx.x >> 5] = v;
    __syncthreads();
    float s = 0.f;
#pragma unroll
    for (int i = 0; i < 8; i++) s += red[i];
    __syncthreads();
    return s;
}
__device__ __forceinline__ float brmin256(float v, float* red) {
#pragma unroll
    for (int off = 16; off > 0; off >>= 1) v = fminf(v, __shfl_down_sync(0xffffffffu, v, off));
    if ((threadIdx.x & 31) == 0) red[threadIdx.x >> 5] = v;
    __syncthreads();
    float s = red[0];
#pragma unroll
    for (int i = 1; i < 8; i++) s = fminf(s, red[i]);
    __syncthreads();
    return s;
}
__device__ __forceinline__ float brmax256(float v, float* red) {
#pragma unroll
    for (int off = 16; off > 0; off >>= 1) v = fmaxf(v, __shfl_down_sync(0xffffffffu, v, off));
    if ((threadIdx.x & 31) == 0) red[threadIdx.x >> 5] = v;
    __syncthreads();
    float s = red[0];
#pragma unroll
    for (int i = 1; i < 8; i++) s = fmaxf(s, red[i]);
    __syncthreads();
    return s;
}

// ---------------- K3: row-split fused Householder (256 thr, 3 barriers/iter)
//                      + split twisted-Sturm bisection ----------------
#define ASTR 132
#define SMEM_EIG ((128 * ASTR + 3 * 128 + 256 + 2 * 128 + 64) * 4)

__global__ void __launch_bounds__(256)
eigen_kernel() {
    extern __shared__ float smE[];
    float* A  = smE;                  // 128 x ASTR
    float* xA = A + 128 * ASTR;       // 128
    float* xB = xA + 128;             // 128
    float* qq = xB + 128;             // 128
    float* pp = qq + 128;             // 256 (per-half praw partials; reused as e2)
    float* dd = pp + 256;             // 128
    float* ee = dd + 128;             // 128
    float* red = ee + 128;            // 64: two parity banks of 16

    const int b = blockIdx.x;
    const int t = threadIdx.x;
    const int r = t & 127;            // row
    const int h = t >> 7;             // column half: [h*64, h*64+64)
    const int w = t >> 5, lane = t & 31;
    const int cbeg = h << 6;
    const float* R = g_Rm + (size_t)b * D * D;

    // load + symmetrize: thread (r,h) fills rows r for its half? simpler: strided rows, col r
    for (int i = h; i < 128; i += 2)
        A[i * ASTR + r] = 0.5f * (R[i * 128 + r] + R[r * 128 + i]);
    __syncthreads();

    // bootstrap: x = col 0; pp[t] = partial dot of row r over cols [cbeg, cbeg+64)
    {
        if (h == 0) xA[r] = (r > 0) ? A[r * ASTR] : 0.0f;
        __syncthreads();
        const float4* Ar4 = (const float4*)(A + r * ASTR + cbeg);
        const float4* X4  = (const float4*)(xA + cbeg);
        float pa[4] = {0.f, 0.f, 0.f, 0.f};
#pragma unroll 4
        for (int q = 0; q < 16; q++) {
            const float4 a = Ar4[q], xv = X4[q];
            pa[q & 3] += a.x * xv.x + a.y * xv.y + a.z * xv.z + a.w * xv.w;
        }
        pp[t] = (pa[0] + pa[1]) + (pa[2] + pa[3]);
        __syncthreads();
    }

    for (int k = 0; k < 126; k++) {
        float* xx = (k & 1) ? xB : xA;
        float* xn = (k & 1) ? xA : xB;
        float* sA = red + (k & 1) * 16;
        float* sB = sA + 8;

        const float xi = xx[r];
        float ws = (h == 0) ? xi * xi : 0.0f;
#pragma unroll
        for (int off = 16; off > 0; off >>= 1) ws += __shfl_down_sync(0xffffffffu, ws, off);
        if (lane == 0) sA[w] = ws;
        __syncthreads();                                  // (1)
        float sig = 0.f;
#pragma unroll
        for (int i = 0; i < 8; i++) sig += sA[i];
        const float x0 = xx[k + 1];
        const float nrm = sqrtf(sig);
        const float alpha = (x0 >= 0.0f) ? -nrm : nrm;
        const float H = sig - alpha * x0;
        const float invH = (H > 1e-32f) ? 1.0f / H : 0.0f;
        if (t == 0) ee[k + 1] = alpha;
        const float ut = xi - ((r == k + 1) ? alpha : 0.0f);
        const float pcomb = pp[r] + pp[r + 128];
        const float p = (r > k) ? (pcomb - alpha * A[r * ASTR + (k + 1)]) * invH : 0.0f;
        float kv = (h == 0) ? ut * p : 0.0f;
#pragma unroll
        for (int off = 16; off > 0; off >>= 1) kv += __shfl_down_sync(0xffffffffu, kv, off);
        if (lane == 0) sB[w] = kv;
        __syncthreads();                                  // (2)
        float Ks = 0.f;
#pragma unroll
        for (int i = 0; i < 8; i++) Ks += sB[i];
        const float Kc = Ks * 0.5f * invH;
        const float qt = (r > k) ? (p - Kc * ut) : 0.0f;
        // redundant q[k+1] from broadcast-ordered values
        const float uk1 = x0 - alpha;
        const float pk1 = (pp[k + 1] + pp[k + 1 + 128]
                           - alpha * A[(k + 1) * ASTR + (k + 1)]) * invH;
        const float qk1 = pk1 - Kc * uk1;
        if (h == 0) {
            qq[r] = qt;
            xn[r] = (r >= k + 2) ? (A[r * ASTR + (k + 1)] - ut * qk1 - qt * uk1) : 0.0f;
        }
        __syncthreads();                                  // (3)
        // fused half-pass: rank-2 update + praw partial over [js, je)
        {
            const int j0 = (k + 1) & ~3;
            const int js = (j0 > cbeg) ? j0 : cbeg;
            const int je = cbeg + 64;
            float pn[4] = {0.f, 0.f, 0.f, 0.f};
            if (r > k && js < je) {
                const int m = (je - js) >> 2;
                float4* Ar4 = (float4*)(A + r * ASTR + js);
                const float4* U4 = (const float4*)(xx + js);
                const float4* Q4 = (const float4*)(qq + js);
                const float4* N4 = (const float4*)(xn + js);
#pragma unroll 4
                for (int q = 0; q < m; q++) {
                    float4 a = Ar4[q];
                    const float4 u4 = U4[q], q4 = Q4[q], n4 = N4[q];
                    a.x -= ut * q4.x + qt * u4.x;
                    a.y -= ut * q4.y + qt * u4.y;
                    a.z -= ut * q4.z + qt * u4.z;
                    a.w -= ut * q4.w + qt * u4.w;
                    pn[q & 3] += a.x * n4.x + a.y * n4.y + a.z * n4.z + a.w * n4.w;
                    Ar4[q] = a;
                }
                // xx held x (not u): fix j=k+1 term in the owning half; xn[k+1]=0 so pn unaffected
                if (k + 1 >= js && k + 1 < je)
                    A[r * ASTR + (k + 1)] += alpha * qt;
            }
            pp[t] = (pn[0] + pn[1]) + (pn[2] + pn[3]);
        }
        // next iteration's barrier (1) orders the pass
    }
    __syncthreads();

    if (h == 0) {
        dd[r] = A[r * ASTR + r];
        if (r == 0) { ee[0] = 0.0f; ee[127] = A[127 * ASTR + 126]; }
    }
    __syncthreads();
    float* e2 = pp;                       // reuse (first 128)
    if (h == 0) e2[r] = ee[r] * ee[r];
    float gl_in = FLT_MAX, gu_in = -FLT_MAX;
    if (h == 0) {
        const float rad = fabsf(ee[r]) + ((r < 127) ? fabsf(ee[r + 1]) : 0.0f);
        gl_in = dd[r] - rad;
        gu_in = dd[r] + rad;
    }
    const float gl = brmin256(gl_in, red);
    const float gu = brmax256(gu_in, red);
    __syncthreads();

    // split twisted-Sturm: h=0 forward chain (rows 0..63), h=1 backward (127..65),
    // parity-buffered exchange in the dead A region, 1 barrier/iter.
    const float pivmin = fmaxf(1e-12f * fmaxf(fabsf(gl), fabsf(gu)), 1e-36f);
    float* qx0 = A;                       // 512 floats (2 parity banks of 256)
    int*   cx0 = (int*)(A + 1024);        // 512 ints
    float lo = gl, hi = gu;
    for (int iter = 0; iter < 26; ++iter) {
        const int par = (iter & 1) * 256;
        float* qx = qx0 + par;
        int*   cx = cx0 + par;
        const float mid = 0.5f * (lo + hi);
        if (h == 0) {
            float qf = dd[0] - mid;
            int cf = (qf < 0.0f);
#pragma unroll 3
            for (int j = 1; j <= 63; j++) {
                if (fabsf(qf) < pivmin) qf = -pivmin;
                qf = dd[j] - mid - __fdividef(e2[j], qf);
                cf += (qf < 0.0f);
            }
            if (fabsf(qf) < pivmin) qf = -pivmin;
            qx[r] = qf; cx[r] = cf;
        } else {
            float qb = dd[127] - mid;
            int cb = (qb < 0.0f);
#pragma unroll 3
            for (int i = 126; i >= 65; i--) {
                if (fabsf(qb) < pivmin) qb = -pivmin;
                qb = dd[i] - mid - __fdividef(e2[i + 1], qb);
                cb += (qb < 0.0f);
            }
            if (fabsf(qb) < pivmin) qb = -pivmin;
            qx[128 + r] = qb; cx[128 + r] = cb;
        }
        __syncthreads();
        const float qf = qx[r], qb = qx[128 + r];
        const float gam = dd[64] - mid - __fdividef(e2[64], qf) - __fdividef(e2[65], qb);
        const int cnt = cx[r] + cx[128 + r] + (gam < 0.0f);
        if (cnt > r) hi = mid; else lo = mid;
    }
    const float lam = 0.5f * (lo + hi);
    const float v = (h == 0 && lam > 0.0f) ? sqrtf(lam) : 0.0f;
    __syncthreads();
    const float s = brs256(v, red);
    if (t == 0) g_partial[b] = s;
}

// ---------------- K4: mean over batch ----------------
__global__ void finalize_kernel(float* out) {
    out[0] = 0.25f * (g_partial[0] + g_partial[1] + g_partial[2] + g_partial[3]);
}

// ---------------- launch ----------------
extern "C" void kernel_launch(void* const* d_in, const int* in_sizes, int n_in,
                              void* d_out, int out_size) {
    const float* x  = (const float*)d_in[0];
    const float* J  = (const float*)d_in[1];
    const int*   ei = (const int*)d_in[2];
    const int E = in_sizes[2] / 2;
    float* out = (float*)d_out;

    cudaFuncSetAttribute(eigen_kernel,
                         cudaFuncAttributeMaxDynamicSharedMemorySize, SMEM_EIG);
    cudaFuncSetAttribute(gemm_kernel,
                         cudaFuncAttributeMaxDynamicSharedMemorySize, GSMEM);

    rowptr_kernel<<<(N_NODES + 1 + 255) / 256, 256>>>(ei, E);

    dim3 ggeo((N_NODES + 127) / 128, BATCH);
    geom_kernel<<<ggeo, 128>>>(x, ei + E);

    dim3 gbuild(N_NODES / 2, BATCH);
    build_kernel<<<gbuild, 256>>>(J, ei + E);

    dim3 ggemm(KS, BATCH);
    gemm_kernel<<<ggemm, 256, GSMEM>>>(J);
    reduce_kernel<<<BATCH * D * D / 256, 256>>>();

    eigen_kernel<<<BATCH, 256, SMEM_EIG>>>();
    finalize_kernel<<<1, 1>>>(out);
}

// round 13
// speedup vs baseline: 1.5480x; 1.0877x over previous
#include <cuda_runtime.h>
#include <math.h>
#include <float.h>
#include <stdint.h>

#define N_NODES 16384
#define D 128
#define BATCH 4
#define WPRIME (0.05f/1.05f)
#define EMAX 98304

#define KS 74
#define PAIRS (N_NODES / 2)
#define STAGES 4
#define SROW 136
#define STAGE_F (24 * SROW)
#define GSMEM (STAGES * STAGE_F * 4)

// ---------------- device scratch ----------------
__device__ float g_Rm[BATCH * D * D];
__device__ float g_Rp[(size_t)BATCH * KS * D * D];
__device__ int   g_rowptr[N_NODES + 1];
__device__ float g_partial[BATCH];
__device__ float g_pan[(size_t)BATCH * N_NODES * 1024];
__device__ float4 g_edgev[(size_t)BATCH * EMAX];
__device__ float g_geo[(size_t)BATCH * N_NODES * 12];

__device__ __forceinline__ uint32_t tf32c(float f) {
    uint32_t u; asm("cvt.rna.tf32.f32 %0, %1;" : "=r"(u) : "f"(f)); return u;
}
__device__ __forceinline__ float tf32f(float f) {
    return __uint_as_float(tf32c(f));
}

// ---------------- K1: CSR row pointers ----------------
__global__ void rowptr_kernel(const int* __restrict__ e0, int E) {
    int n = blockIdx.x * blockDim.x + threadIdx.x;
    if (n > N_NODES) return;
    int lo = 0, hi = E;
    while (lo < hi) {
        int mid = (lo + hi) >> 1;
        if (e0[mid] < n) lo = mid + 1; else hi = mid;
    }
    g_rowptr[n] = lo;
}

// ---------------- K1b: per-node geometry ----------------
__global__ void geom_kernel(const float* __restrict__ x, const int* __restrict__ e1arr) {
    const int n = blockIdx.x * blockDim.x + threadIdx.x;
    const int b = blockIdx.y;
    if (n >= N_NODES) return;

    const float* xb = x + (size_t)b * N_NODES * 3;
    const float xn0 = xb[3 * n], xn1 = xb[3 * n + 1], xn2 = xb[3 * n + 2];
    float4* ev = g_edgev + (size_t)b * EMAX;

    float deg = 0.f, s0 = 0.f, s1 = 0.f, s2 = 0.f, G = 0.f;
    float c00 = 0.f, c01 = 0.f, c02 = 0.f, c11 = 0.f, c12 = 0.f, c22 = 0.f;

    const int eBeg = g_rowptr[n], eEnd = g_rowptr[n + 1];
    for (int e = eBeg; e < eEnd; ++e) {
        const int m = e1arr[e];
        const float v0 = xn0 - xb[3 * m];
        const float v1 = xn1 - xb[3 * m + 1];
        const float v2 = xn2 - xb[3 * m + 2];
        ev[e] = make_float4(v0, v1, v2, 0.0f);
        deg += 1.0f; s0 += v0; s1 += v1; s2 += v2;
        const float vv = v0 * v0 + v1 * v1 + v2 * v2;
        G += vv;
        c00 += vv - v0 * v0; c01 -= v0 * v1; c02 -= v0 * v2;
        c11 += vv - v1 * v1; c12 -= v1 * v2; c22 += vv - v2 * v2;
    }

    const float l00 = sqrtf(c00);
    const float il00 = 1.0f / l00;
    const float l10 = c01 * il00, l20 = c02 * il00;
    const float l11 = sqrtf(c11 - l10 * l10);
    const float il11 = 1.0f / l11;
    const float l21 = (c12 - l20 * l10) * il11;
    const float l22 = sqrtf(c22 - l20 * l20 - l21 * l21);
    const float il22 = 1.0f / l22;
    const float Ginv = (G < 1e-6f) ? 0.0f : 1.0f / G;

    float* ge = g_geo + ((size_t)b * N_NODES + n) * 12;
    ge[0] = deg; ge[1] = s0; ge[2] = s1; ge[3] = s2;
    ge[4] = il00; ge[5] = l10; ge[6] = il11;
    ge[7] = l20; ge[8] = l21; ge[9] = il22;
    ge[10] = WPRIME * Ginv; ge[11] = 0.0f;
}

// ---------------- K2a: build panels — one WARP per node, float4 per lane ----------------
__global__ void __launch_bounds__(256)
build_kernel(const float* __restrict__ J, const int* __restrict__ e1arr) {
    const int b = blockIdx.y;
    const int warp = threadIdx.x >> 5;
    const int lane = threadIdx.x & 31;
    const int n = blockIdx.x * 8 + warp;
    const int c4 = lane * 4;                       // columns c4..c4+3

    const float* Jb = J + (size_t)b * N_NODES * 3 * D;
    const float4* ev = g_edgev + (size_t)b * EMAX;

    const float* JnR = Jb + (size_t)(3 * n) * D + c4;
    const float4 Jn0 = *(const float4*)(JnR);
    const float4 Jn1 = *(const float4*)(JnR + D);
    const float4 Jn2 = *(const float4*)(JnR + 2 * D);

    float4 nb0 = {0,0,0,0}, nb1 = {0,0,0,0}, nb2 = {0,0,0,0};
    float4 T0 = {0,0,0,0}, T1 = {0,0,0,0}, T2 = {0,0,0,0}, uu = {0,0,0,0};

    const int eBeg = g_rowptr[n], eEnd = g_rowptr[n + 1];
    const int degn = eEnd - eBeg;

#define ACC_NEIGH(v, m0, m1, m2)                                           \
    do {                                                                   \
        nb0.x += m0.x; nb0.y += m0.y; nb0.z += m0.z; nb0.w += m0.w;        \
        nb1.x += m1.x; nb1.y += m1.y; nb1.z += m1.z; nb1.w += m1.w;        \
        nb2.x += m2.x; nb2.y += m2.y; nb2.z += m2.z; nb2.w += m2.w;        \
        T0.x += v.y * m2.x - v.z * m1.x;  T0.y += v.y * m2.y - v.z * m1.y; \
        T0.z += v.y * m2.z - v.z * m1.z;  T0.w += v.y * m2.w - v.z * m1.w; \
        T1.x += v.z * m0.x - v.x * m2.x;  T1.y += v.z * m0.y - v.x * m2.y; \
        T1.z += v.z * m0.z - v.x * m2.z;  T1.w += v.z * m0.w - v.x * m2.w; \
        T2.x += v.x * m1.x - v.y * m0.x;  T2.y += v.x * m1.y - v.y * m0.y; \
        T2.z += v.x * m1.z - v.y * m0.z;  T2.w += v.x * m1.w - v.y * m0.w; \
        uu.x += v.x * m0.x + v.y * m1.x + v.z * m2.x;                      \
        uu.y += v.x * m0.y + v.y * m1.y + v.z * m2.y;                      \
        uu.z += v.x * m0.z + v.y * m1.z + v.z * m2.z;                      \
        uu.w += v.x * m0.w + v.y * m1.w + v.z * m2.w;                      \
    } while (0)

    if (degn == 6) {
        int mm[6];
#pragma unroll
        for (int i = 0; i < 6; i++) mm[i] = e1arr[eBeg + i];
        float4 vv6[6];
#pragma unroll
        for (int i = 0; i < 6; i++) vv6[i] = ev[eBeg + i];
#pragma unroll
        for (int i = 0; i < 6; i += 2) {
            const float* JmA = Jb + (size_t)(3 * mm[i]) * D + c4;
            const float* JmB = Jb + (size_t)(3 * mm[i + 1]) * D + c4;
            const float4 a0 = *(const float4*)(JmA);
            const float4 a1 = *(const float4*)(JmA + D);
            const float4 a2 = *(const float4*)(JmA + 2 * D);
            const float4 b0 = *(const float4*)(JmB);
            const float4 b1 = *(const float4*)(JmB + D);
            const float4 b2 = *(const float4*)(JmB + 2 * D);
            { const float4 v = vv6[i];     ACC_NEIGH(v, a0, a1, a2); }
            { const float4 v = vv6[i + 1]; ACC_NEIGH(v, b0, b1, b2); }
        }
    } else {
        for (int e = eBeg; e < eEnd; ++e) {
            const int m = e1arr[e];
            const float4 v = ev[e];
            const float* Jm = Jb + (size_t)(3 * m) * D + c4;
            const float4 m0 = *(const float4*)(Jm);
            const float4 m1 = *(const float4*)(Jm + D);
            const float4 m2 = *(const float4*)(Jm + 2 * D);
            ACC_NEIGH(v, m0, m1, m2);
        }
    }
#undef ACC_NEIGH

    const float* ge = g_geo + ((size_t)b * N_NODES + n) * 12;
    const float deg = ge[0], s0 = ge[1], s1 = ge[2], s2 = ge[3];
    const float il00 = ge[4], l10 = ge[5], il11 = ge[6];
    const float l20 = ge[7], l21 = ge[8], il22 = ge[9];
    const float wGinv = ge[10];

    float* P = g_pan + ((size_t)b * N_NODES + n) * 1024 + c4;
    float4 oZ0, oZ1, oZ2, oy, oL0, oL1, oL2, og;

#define COL(F)                                                              \
    {                                                                       \
        const float jn0 = Jn0.F, jn1 = Jn1.F, jn2 = Jn2.F;                  \
        const float LJ0 = 2.0f * (deg * jn0 - nb0.F);                       \
        const float LJ1 = 2.0f * (deg * jn1 - nb1.F);                       \
        const float LJ2 = 2.0f * (deg * jn2 - nb2.F);                       \
        const float B0 = T0.F + s2 * jn1 - s1 * jn2;                        \
        const float B1 = T1.F - s2 * jn0 + s0 * jn2;                        \
        const float B2 = T2.F + s1 * jn0 - s0 * jn1;                        \
        const float y = uu.F - (s0 * jn0 + s1 * jn1 + s2 * jn2);            \
        const float Z0 = B0 * il00;                                         \
        const float Z1 = (B1 - l10 * Z0) * il11;                            \
        const float Z2 = (B2 - l20 * Z0 - l21 * Z1) * il22;                 \
        oZ0.F = tf32f(Z0); oZ1.F = tf32f(Z1); oZ2.F = tf32f(Z2);            \
        oy.F = tf32f(y);                                                    \
        oL0.F = tf32f(LJ0); oL1.F = tf32f(LJ1); oL2.F = tf32f(LJ2);         \
        og.F = tf32f(-wGinv * y);                                           \
    }
    COL(x) COL(y) COL(z) COL(w)
#undef COL

    *(float4*)(P + 0 * 128) = oZ0;  *(float4*)(P + 1 * 128) = oZ1;
    *(float4*)(P + 2 * 128) = oZ2;  *(float4*)(P + 3 * 128) = oy;
    *(float4*)(P + 4 * 128) = oL0;  *(float4*)(P + 5 * 128) = oL1;
    *(float4*)(P + 6 * 128) = oL2;  *(float4*)(P + 7 * 128) = og;
}

// ---------------- K2b: TF32 split-K GEMM (unchanged, known good) ----------------
__device__ __forceinline__ void cp_async16(void* dst_smem, const void* src) {
    uint32_t d = (uint32_t)__cvta_generic_to_shared(dst_smem);
    asm volatile("cp.async.cg.shared.global [%0], [%1], 16;" :: "r"(d), "l"(src));
}
__device__ __forceinline__ void cp_commit() { asm volatile("cp.async.commit_group;"); }
template<int NN> __device__ __forceinline__ void cp_wait() {
    asm volatile("cp.async.wait_group %0;" :: "n"(NN));
}
__device__ __forceinline__ void mma_tf32(float* d, uint32_t a0, uint32_t a1,
                                         uint32_t a2, uint32_t a3,
                                         uint32_t b0, uint32_t b1) {
    asm volatile(
        "mma.sync.aligned.m16n8k8.row.col.f32.tf32.tf32.f32 "
        "{%0,%1,%2,%3}, {%4,%5,%6,%7}, {%8,%9}, {%0,%1,%2,%3};"
        : "+f"(d[0]), "+f"(d[1]), "+f"(d[2]), "+f"(d[3])
        : "r"(a0), "r"(a1), "r"(a2), "r"(a3), "r"(b0), "r"(b1));
}

__global__ void __launch_bounds__(256, 2)
gemm_kernel(const float* __restrict__ J) {
    extern __shared__ float smg[];

    const int b = blockIdx.y, ks = blockIdx.x;
    const int t = threadIdx.x;
    const int wid = t >> 5, lane = t & 31;
    const int wm = (wid >> 2) * 64;
    const int wn = (wid & 3) * 32;
    const int r0 = lane >> 2, kc = lane & 3;

    const int pbeg = (ks * PAIRS) / KS;
    const int pend = ((ks + 1) * PAIRS) / KS;
    const int NITv = pend - pbeg;
    const int nodeBase = 2 * pbeg;

    const float* Jb = J + (size_t)b * N_NODES * 3 * D;
    const float* Pb = g_pan + ((size_t)b * N_NODES + nodeBase) * 1024;

    for (int idx = t; idx < STAGES * 2 * SROW; idx += 256) {
        const int s = idx / (2 * SROW);
        const int rem = idx - s * 2 * SROW;
        const int row = (rem < SROW) ? 7 : 19;
        smg[s * STAGE_F + row * SROW + (rem % SROW)] = 0.0f;
    }

    const int      brow0 = (kc < 3) ? 8 + kc : 3;
    const uint32_t bmsk0 = (kc < 3) ? 0u : 0x80000000u;
    const int      brow1 = (kc < 2) ? 4 + kc : ((kc == 2) ? 11 : 7);
    const uint32_t bmsk1 = (kc < 2) ? 0x80000000u : 0u;

    float acc[4][4][4];
#pragma unroll
    for (int i = 0; i < 4; i++)
#pragma unroll
        for (int j = 0; j < 4; j++)
#pragma unroll
            for (int r = 0; r < 4; r++) acc[i][j][r] = 0.0f;

    const int prow = t >> 5;
    const int scol = (t & 31) * 4;
    const int srowP = (prow < 4) ? 3 + prow : 4 + prow;

    auto issue = [&](int it) {
        const int stg = it & (STAGES - 1);
        float* SB = smg + stg * STAGE_F;
        const float* p0 = Pb + (size_t)(2 * it) * 1024;
        cp_async16(SB + srowP * SROW + scol, p0 + t * 4);
        cp_async16(SB + (12 + srowP) * SROW + scol, p0 + 1024 + t * 4);
        if (t < 96) {
            const float* j0 = Jb + (size_t)(3 * (nodeBase + 2 * it)) * D;
            cp_async16(SB + prow * SROW + scol, j0 + t * 4);
            cp_async16(SB + (12 + prow) * SROW + scol, j0 + 384 + t * 4);
        }
    };

    for (int s = 0; s < STAGES - 1; s++) { if (s < NITv) issue(s); cp_commit(); }

    for (int it = 0; it < NITv; ++it) {
        const int stg = it & (STAGES - 1);
        if (it + STAGES - 1 < NITv) issue(it + STAGES - 1);
        cp_commit();
        cp_wait<STAGES - 1>();
        __syncthreads();

        const float* S0 = smg + stg * STAGE_F;
#pragma unroll
        for (int g = 0; g < 2; ++g) {
            const float* S = S0 + g * 12 * SROW;

            uint32_t bb[4][2];
#pragma unroll
            for (int nt = 0; nt < 4; nt++) {
                const int n = wn + nt * 8 + r0;
                bb[nt][0] = __float_as_uint(S[brow0 * SROW + n]) ^ bmsk0;
                bb[nt][1] = __float_as_uint(S[brow1 * SROW + n]) ^ bmsk1;
            }
#pragma unroll
            for (int mt = 0; mt < 4; mt++) {
                const int m = wm + mt * 16 + r0;
                const uint32_t a0 = tf32c(S[kc * SROW + m]);
                const uint32_t a1 = tf32c(S[kc * SROW + m + 8]);
                const uint32_t a2 = __float_as_uint(S[(kc + 4) * SROW + m]);
                const uint32_t a3 = __float_as_uint(S[(kc + 4) * SROW + m + 8]);
#pragma unroll
                for (int nt = 0; nt < 4; nt++)
                    mma_tf32(acc[mt][nt], a0, a1, a2, a3, bb[nt][0], bb[nt][1]);
            }
        }
        __syncthreads();
    }

    float* out = g_Rp + (((size_t)b * KS + ks) << 14);
#pragma unroll
    for (int mt = 0; mt < 4; mt++) {
        const int m = wm + mt * 16 + r0;
#pragma unroll
        for (int nt = 0; nt < 4; nt++) {
            const int n = wn + nt * 8 + 2 * kc;
            *(float2*)&out[m * 128 + n]       = make_float2(acc[mt][nt][0], acc[mt][nt][1]);
            *(float2*)&out[(m + 8) * 128 + n] = make_float2(acc[mt][nt][2], acc[mt][nt][3]);
        }
    }
}

// ---------------- K2c: reduce split-K partials (float4) ----------------
__global__ void reduce_kernel() {
    const int idx = blockIdx.x * 256 + threadIdx.x;   // 0..16383 float4 slots
    const int b = idx >> 12;                           // 4096 float4 per batch
    const int e = idx & 4095;
    const float4* p = (const float4*)(g_Rp + ((size_t)b * KS << 14)) + e;
    float4 s = {0, 0, 0, 0};
#pragma unroll 8
    for (int k = 0; k < KS; k++) {
        const float4 v = p[(size_t)k << 12];
        s.x += v.x; s.y += v.y; s.z += v.z; s.w += v.w;
    }
    ((float4*)g_Rm)[idx] = s;
}

// ---------------- 256-thread reductions for eigen tail ----------------
__device__ __forceinline__ float brs256(float v, float* red) {
#pragma unroll
    for (int off = 16; off > 0; off >>= 1) v += __shfl_down_sync(0xffffffffu, v, off);
    if ((threadIdx.x & 31) == 0) red[threadIdx.x >> 5] = v;
    __syncthreads();
    float s = 0.f;
#pragma unroll
    for (int i = 0; i < 8; i++) s += red[i];
    __syncthreads();
    return s;
}
__device__ __forceinline__ float brmin256(float v, float* red) {
#pragma unroll
    for (int off = 16; off > 0; off >>= 1) v = fminf(v, __shfl_down_sync(0xffffffffu, v, off));
    if ((threadIdx.x & 31) == 0) red[threadIdx.x >> 5] = v;
    __syncthreads();
    float s = red[0];
#pragma unroll
    for (int i = 1; i < 8; i++) s = fminf(s, red[i]);
    __syncthreads();
    return s;
}
__device__ __forceinline__ float brmax256(float v, float* red) {
#pragma unroll
    for (int off = 16; off > 0; off >>= 1) v = fmaxf(v, __shfl_down_sync(0xffffffffu, v, off));
    if ((threadIdx.x & 31) == 0) red[threadIdx.x >> 5] = v;
    __syncthreads();
    float s = red[0];
#pragma unroll
    for (int i = 1; i < 8; i++) s = fmaxf(s, red[i]);
    __syncthreads();
    return s;
}

// ---------------- K3: row-split Householder, 2 barriers/iter + split twisted Sturm ----------------
#define ASTR 132
#define SMEM_EIG ((128 * ASTR + 3 * 128 + 256 + 2 * 128 + 96) * 4)

__global__ void __launch_bounds__(256)
eigen_kernel() {
    extern __shared__ float smE[];
    float* A  = smE;                  // 128 x ASTR
    float* xA = A + 128 * ASTR;       // 128
    float* xB = xA + 128;             // 128
    float* qq = xB + 128;             // 128
    float* pp = qq + 128;             // 256 (half-dot partials; later e2)
    float* dd = pp + 256;             // 128
    float* ee = dd + 128;             // 128
    float* red = ee + 128;            // 96: loop parity banks [0..63], tail [64..95]

    const int b = blockIdx.x;
    const int t = threadIdx.x;
    const int r = t & 127;
    const int h = t >> 7;
    const int w = t >> 5, lane = t & 31;
    const int cbeg = h << 6;
    const float* R = g_Rm + (size_t)b * D * D;

    for (int i = h; i < 128; i += 2)
        A[i * ASTR + r] = 0.5f * (R[i * 128 + r] + R[r * 128 + i]);
    __syncthreads();

    // bootstrap: x = col 0; pp[t] = half-row dot; keep register copy pnreg
    float pnreg;
    {
        if (h == 0) xA[r] = (r > 0) ? A[r * ASTR] : 0.0f;
        __syncthreads();
        const float4* Ar4 = (const float4*)(A + r * ASTR + cbeg);
        const float4* X4  = (const float4*)(xA + cbeg);
        float pa[4] = {0.f, 0.f, 0.f, 0.f};
#pragma unroll 4
        for (int q = 0; q < 16; q++) {
            const float4 a = Ar4[q], xv = X4[q];
            pa[q & 3] += a.x * xv.x + a.y * xv.y + a.z * xv.z + a.w * xv.w;
        }
        pnreg = (pa[0] + pa[1]) + (pa[2] + pa[3]);
        pp[t] = pnreg;
        __syncthreads();
    }

    for (int k = 0; k < 126; k++) {
        float* xx = (k & 1) ? xB : xA;
        float* xn = (k & 1) ? xA : xB;
        float* sA = red + (k & 1) * 32;      // 8 slots ws, 8 slots kv2
        float* sB = sA + 8;

        const float xi = xx[r];              // ordered by prev barrier (2)
        float ws  = (h == 0) ? xi * xi : 0.0f;
        float kv2 = xi * pnreg;              // own register — no cross-thread read
#pragma unroll
        for (int off = 16; off > 0; off >>= 1) {
            ws  += __shfl_down_sync(0xffffffffu, ws, off);
            kv2 += __shfl_down_sync(0xffffffffu, kv2, off);
        }
        if (lane == 0) { sA[w] = ws; sB[w] = kv2; }
        __syncthreads();                                  // (1)
        float sig = 0.f, S2 = 0.f;
#pragma unroll
        for (int i = 0; i < 8; i++) { sig += sA[i]; S2 += sB[i]; }
        const float x0 = xx[k + 1];
        const float nrm = sqrtf(sig);
        const float alpha = (x0 >= 0.0f) ? -nrm : nrm;
        const float H = sig - alpha * x0;
        const float invH = (H > 1e-32f) ? 1.0f / H : 0.0f;
        if (t == 0) ee[k + 1] = alpha;
        const float praw_k1 = pp[k + 1] + pp[k + 1 + 128];       // ordered by (1)
        const float dk1 = A[(k + 1) * ASTR + (k + 1)];           // ordered by (1)
        const float uAu = S2 - 2.0f * alpha * praw_k1 + alpha * alpha * dk1;
        const float Kc = uAu * invH * 0.5f * invH;
        const float ut = xi - ((r == k + 1) ? alpha : 0.0f);
        const float pcomb = pp[r] + pp[r + 128];
        const float p = (r > k) ? (pcomb - alpha * A[r * ASTR + (k + 1)]) * invH : 0.0f;
        const float qt = (r > k) ? (p - Kc * ut) : 0.0f;
        const float uk1 = x0 - alpha;
        const float pk1 = (praw_k1 - alpha * dk1) * invH;
        const float qk1 = pk1 - Kc * uk1;
        if (h == 0) {
            qq[r] = qt;
            xn[r] = (r >= k + 2) ? (A[r * ASTR + (k + 1)] - ut * qk1 - qt * uk1) : 0.0f;
        }
        __syncthreads();                                  // (2)
        // fused half-pass: rank-2 update + next half-dot
        {
            const int j0 = (k + 1) & ~3;
            const int js = (j0 > cbeg) ? j0 : cbeg;
            const int je = cbeg + 64;
            float pn[4] = {0.f, 0.f, 0.f, 0.f};
            if (r > k && js < je) {
                const int m = (je - js) >> 2;
                float4* Ar4 = (float4*)(A + r * ASTR + js);
                const float4* U4 = (const float4*)(xx + js);
                const float4* Q4 = (const float4*)(qq + js);
                const float4* N4 = (const float4*)(xn + js);
#pragma unroll 4
                for (int q = 0; q < m; q++) {
                    float4 a = Ar4[q];
                    const float4 u4 = U4[q], q4 = Q4[q], n4 = N4[q];
                    a.x -= ut * q4.x + qt * u4.x;
                    a.y -= ut * q4.y + qt * u4.y;
                    a.z -= ut * q4.z + qt * u4.z;
                    a.w -= ut * q4.w + qt * u4.w;
                    pn[q & 3] += a.x * n4.x + a.y * n4.y + a.z * n4.z + a.w * n4.w;
                    Ar4[q] = a;
                }
                if (k + 1 >= js && k + 1 < je)
                    A[r * ASTR + (k + 1)] += alpha * qt;   // xx held x, not u
            }
            pnreg = (pn[0] + pn[1]) + (pn[2] + pn[3]);
            pp[t] = pnreg;
        }
        // next iteration's barrier (1) orders the pass
    }
    __syncthreads();

    if (h == 0) {
        dd[r] = A[r * ASTR + r];
        if (r == 0) { ee[0] = 0.0f; ee[127] = A[127 * ASTR + 126]; }
    }
    __syncthreads();
    float* e2 = pp;
    if (h == 0) e2[r] = ee[r] * ee[r];
    float gl_in = FLT_MAX, gu_in = -FLT_MAX;
    if (h == 0) {
        const float rad = fabsf(ee[r]) + ((r < 127) ? fabsf(ee[r + 1]) : 0.0f);
        gl_in = dd[r] - rad;
        gu_in = dd[r] + rad;
    }
    const float gl = brmin256(gl_in, red + 64);
    const float gu = brmax256(gu_in, red + 64);
    __syncthreads();

    const float pivmin = fmaxf(1e-12f * fmaxf(fabsf(gl), fabsf(gu)), 1e-36f);
    float* qx0 = A;
    int*   cx0 = (int*)(A + 1024);
    float lo = gl, hi = gu;
    for (int iter = 0; iter < 26; ++iter) {
        const int par = (iter & 1) * 256;
        float* qx = qx0 + par;
        int*   cx = cx0 + par;
        const float mid = 0.5f * (lo + hi);
        if (h == 0) {
            float qf = dd[0] - mid;
            int cf = (qf < 0.0f);
#pragma unroll 3
            for (int j = 1; j <= 63; j++) {
                if (fabsf(qf) < pivmin) qf = -pivmin;
                qf = dd[j] - mid - __fdividef(e2[j], qf);
                cf += (qf < 0.0f);
            }
            if (fabsf(qf) < pivmin) qf = -pivmin;
            qx[r] = qf; cx[r] = cf;
        } else {
            float qb = dd[127] - mid;
            int cb = (qb < 0.0f);
#pragma unroll 3
            for (int i = 126; i >= 65; i--) {
                if (fabsf(qb) < pivmin) qb = -pivmin;
                qb = dd[i] - mid - __fdividef(e2[i + 1], qb);
                cb += (qb < 0.0f);
            }
            if (fabsf(qb) < pivmin) qb = -pivmin;
            qx[128 + r] = qb; cx[128 + r] = cb;
        }
        __syncthreads();
        const float qf = qx[r], qb = qx[128 + r];
        const float gam = dd[64] - mid - __fdividef(e2[64], qf) - __fdividef(e2[65], qb);
        const int cnt = cx[r] + cx[128 + r] + (gam < 0.0f);
        if (cnt > r) hi = mid; else lo = mid;
    }
    const float lam = 0.5f * (lo + hi);
    const float v = (h == 0 && lam > 0.0f) ? sqrtf(lam) : 0.0f;
    __syncthreads();
    const float s = brs256(v, red + 64);
    if (t == 0) g_partial[b] = s;
}

// ---------------- K4: mean over batch ----------------
__global__ void finalize_kernel(float* out) {
    out[0] = 0.25f * (g_partial[0] + g_partial[1] + g_partial[2] + g_partial[3]);
}

// ---------------- launch ----------------
extern "C" void kernel_launch(void* const* d_in, const int* in_sizes, int n_in,
                              void* d_out, int out_size) {
    const float* x  = (const float*)d_in[0];
    const float* J  = (const float*)d_in[1];
    const int*   ei = (const int*)d_in[2];
    const int E = in_sizes[2] / 2;
    float* out = (float*)d_out;

    cudaFuncSetAttribute(eigen_kernel,
                         cudaFuncAttributeMaxDynamicSharedMemorySize, SMEM_EIG);
    cudaFuncSetAttribute(gemm_kernel,
                         cudaFuncAttributeMaxDynamicSharedMemorySize, GSMEM);

    rowptr_kernel<<<(N_NODES + 1 + 255) / 256, 256>>>(ei, E);

    dim3 ggeo((N_NODES + 127) / 128, BATCH);
    geom_kernel<<<ggeo, 128>>>(x, ei + E);

    dim3 gbuild(N_NODES / 8, BATCH);
    build_kernel<<<gbuild, 256>>>(J, ei + E);

    dim3 ggemm(KS, BATCH);
    gemm_kernel<<<ggemm, 256, GSMEM>>>(J);
    reduce_kernel<<<BATCH * D * D / 4 / 256, 256>>>();

    eigen_kernel<<<BATCH, 256, SMEM_EIG>>>();
    finalize_kernel<<<1, 1>>>(out);
}